// round 2
// baseline (speedup 1.0000x reference)
#include <cuda_runtime.h>
#include <math.h>

#define N_NODES 8192
#define INDIM   768
#define D1      256
#define D2      128
#define NHEAD   2
#define ALPHAF  0.2f
#define NPAIRS  100000
#define NW      (N_NODES/32)   // 256 adjacency words per row

// ---------------- static device scratch (no allocation) ----------------
__device__ unsigned g_adj[N_NODES * NW];

__device__ float g_H[NHEAD][N_NODES * D1];
__device__ float g_s1[NHEAD][N_NODES], g_t1[NHEAD][N_NODES];
__device__ float g_p1[NHEAD][N_NODES], g_q1[NHEAD][N_NODES];
__device__ float g_b1[NHEAD][N_NODES], g_d1[NHEAD][N_NODES];
__device__ float g_th1[NHEAD][N_NODES];
__device__ float g_num1[NHEAD][N_NODES * D1];
__device__ float g_den1[NHEAD][N_NODES];

__device__ float g_z[N_NODES * D1];
__device__ float g_hc[N_NODES * D2];
__device__ float g_s2[N_NODES], g_t2[N_NODES];
__device__ float g_P2[N_NODES], g_R2[N_NODES], g_Es[N_NODES];
__device__ float g_B2[N_NODES], g_Et[N_NODES], g_th2[N_NODES];
__device__ float g_num2[N_NODES * D2];
__device__ float g_den2[N_NODES];
__device__ float g_embed[N_NODES * D2];

__device__ float g_mid[2][N_NODES * D2];
__device__ float g_tf[N_NODES * 64];
__device__ float g_tg[N_NODES * 64];

__device__ __forceinline__ float eluf(float x) { return x > 0.f ? x : (expf(x) - 1.f); }

// ---------------- 1. pack adjacency into bits ----------------
__global__ void k_pack(const int* __restrict__ adj) {
    int w = blockIdx.x * 8 + (threadIdx.x >> 5);       // word id
    int lane = threadIdx.x & 31;
    int e = w * 32 + lane;                             // element id (< 2^26)
    int v = adj[e];
    unsigned m = __ballot_sync(0xffffffffu, v > 0);
    if (lane == 0) g_adj[w] = m;
}

// ---------------- 2. generic fp32 GEMM: C = act(A@W + bias) ----------------
// BM=64, BN=64, BK=32, 256 threads, 4x4 micro-tile. M%64==0, K%32==0, N%64==0.
template <int ACT>
__global__ __launch_bounds__(256) void k_gemm(
    const float* __restrict__ A, const float* __restrict__ W,
    const float* __restrict__ bias, float* __restrict__ C,
    int M, int K, int N, long long astride, long long wstride, long long cstride)
{
    const float* Az = A + (long long)blockIdx.z * astride;
    const float* Wz = W + (long long)blockIdx.z * wstride;
    float*       Cz = C + (long long)blockIdx.z * cstride;

    __shared__ float a_s[32][65];
    __shared__ float w_s[32][64];

    int m0 = blockIdx.x * 64, n0 = blockIdx.y * 64;
    int tid = threadIdx.x;
    int ty = tid >> 4, tx = tid & 15;

    float acc[4][4];
#pragma unroll
    for (int r = 0; r < 4; r++)
#pragma unroll
        for (int c = 0; c < 4; c++) acc[r][c] = 0.f;

    for (int k0 = 0; k0 < K; k0 += 32) {
        {   // A tile -> transposed smem
            int m = tid & 63, kq = (tid >> 6) * 8;
            const float* ap = Az + (long long)(m0 + m) * K + k0 + kq;
            float4 v0 = *(const float4*)ap;
            float4 v1 = *(const float4*)(ap + 4);
            a_s[kq + 0][m] = v0.x; a_s[kq + 1][m] = v0.y;
            a_s[kq + 2][m] = v0.z; a_s[kq + 3][m] = v0.w;
            a_s[kq + 4][m] = v1.x; a_s[kq + 5][m] = v1.y;
            a_s[kq + 6][m] = v1.z; a_s[kq + 7][m] = v1.w;
        }
        {   // W tile
            int k = tid >> 3, nq = (tid & 7) * 8;
            const float* wp = Wz + (long long)(k0 + k) * N + n0 + nq;
            float4 v0 = *(const float4*)wp;
            float4 v1 = *(const float4*)(wp + 4);
            *(float4*)&w_s[k][nq] = v0;
            *(float4*)&w_s[k][nq + 4] = v1;
        }
        __syncthreads();
#pragma unroll 8
        for (int k = 0; k < 32; k++) {
            float av[4];
#pragma unroll
            for (int r = 0; r < 4; r++) av[r] = a_s[k][ty * 4 + r];
            float4 wv = *(float4*)&w_s[k][tx * 4];
            float bv[4] = {wv.x, wv.y, wv.z, wv.w};
#pragma unroll
            for (int r = 0; r < 4; r++)
#pragma unroll
                for (int c = 0; c < 4; c++) acc[r][c] += av[r] * bv[c];
        }
        __syncthreads();
    }

    float bb[4] = {0.f, 0.f, 0.f, 0.f};
    if (bias) {
#pragma unroll
        for (int c = 0; c < 4; c++) bb[c] = bias[n0 + tx * 4 + c];
    }
#pragma unroll
    for (int r = 0; r < 4; r++) {
        int row = m0 + ty * 4 + r;
        float4 o;
        float v0 = acc[r][0] + bb[0], v1 = acc[r][1] + bb[1];
        float v2 = acc[r][2] + bb[2], v3 = acc[r][3] + bb[3];
        if (ACT == 1) { v0 = eluf(v0); v1 = eluf(v1); v2 = eluf(v2); v3 = eluf(v3); }
        o.x = v0; o.y = v1; o.z = v2; o.w = v3;
        *(float4*)&Cz[(long long)row * N + n0 + tx * 4] = o;
    }
}

// ---------------- 3. s,t per node per head ----------------
__global__ void k_st(const float* __restrict__ head_a) {
    int h = blockIdx.y;
    int warp = threadIdx.x >> 5, lane = threadIdx.x & 31;
    int i = blockIdx.x * 8 + warp;
    const float* H = g_H[h] + (long long)i * D1;
    const float* ah = head_a + h * 2 * D1;
    float s = 0.f, t = 0.f;
#pragma unroll
    for (int d = lane; d < D1; d += 32) {
        float hv = H[d];
        s += hv * ah[d];
        t += hv * ah[D1 + d];
    }
#pragma unroll
    for (int o = 16; o; o >>= 1) {
        s += __shfl_xor_sync(0xffffffffu, s, o);
        t += __shfl_xor_sync(0xffffffffu, t, o);
    }
    if (!lane) { g_s1[h][i] = s; g_t1[h][i] = t; }
}

// ---------------- 4. GAT1 per-node softmax factors ----------------
__global__ void k_fac1() {
    int h = blockIdx.x;
    __shared__ float red[1024];
    float m = -1e30f;
    for (int i = threadIdx.x; i < N_NODES; i += 1024) m = fmaxf(m, g_t1[h][i]);
    red[threadIdx.x] = m;
    __syncthreads();
    for (int s = 512; s; s >>= 1) {
        if (threadIdx.x < s) red[threadIdx.x] = fmaxf(red[threadIdx.x], red[threadIdx.x + s]);
        __syncthreads();
    }
    float tmax = red[0];
    for (int i = threadIdx.x; i < N_NODES; i += 1024) {
        float s_ = g_s1[h][i], t_ = g_t1[h][i];
        float v = s_ + tmax;
        float mm = v > 0.f ? v : ALPHAF * v;     // lrelu(s+tmax) = row max
        g_p1[h][i]  = expf(v - mm);              // <= 1
        g_q1[h][i]  = expf(ALPHAF * v - mm);     // <= 1
        g_b1[h][i]  = expf(t_ - tmax);           // <= 1
        g_d1[h][i]  = expf(ALPHAF * (t_ - tmax));
        g_th1[h][i] = -s_;
    }
}

// ---------------- 5. GAT1 pass: num = W.h, den = W.1 ----------------
// BM=128 rows, BN=64 cols of D1, BK=32 (one adj word). 256 thr, 8x4 micro.
__global__ __launch_bounds__(256) void k_gat1() {
    int h = blockIdx.z;
    int i0 = blockIdx.x * 128, n0 = blockIdx.y * 64;

    __shared__ float w_s[32][128];
    __shared__ float h_s[32][64];
    __shared__ float bcol[32], dcol[32], tcol[32];

    int tid = threadIdx.x;
    int r = tid & 127, kh = (tid >> 7) * 16;
    float p_r  = g_p1[h][i0 + r];
    float q_r  = g_q1[h][i0 + r];
    float th_r = g_th1[h][i0 + r];
    const unsigned* adjrow = g_adj + (long long)(i0 + r) * NW;

    int ty = tid >> 4, tx = tid & 15;
    float acc[8][4];
#pragma unroll
    for (int a = 0; a < 8; a++)
#pragma unroll
        for (int b = 0; b < 4; b++) acc[a][b] = 0.f;
    float den = 0.f;
    const float* Hh = g_H[h];

    for (int jt = 0; jt < NW; jt++) {
        int j0 = jt * 32;
        if (tid < 32)       bcol[tid]      = g_b1[h][j0 + tid];
        else if (tid < 64)  dcol[tid - 32] = g_d1[h][j0 + tid - 32];
        else if (tid < 96)  tcol[tid - 64] = g_t1[h][j0 + tid - 64];
        {
            int k = tid >> 3, nq = (tid & 7) * 8;
            const float* hp = Hh + (long long)(j0 + k) * D1 + n0 + nq;
            float4 v0 = *(const float4*)hp;
            float4 v1 = *(const float4*)(hp + 4);
            *(float4*)&h_s[k][nq] = v0;
            *(float4*)&h_s[k][nq + 4] = v1;
        }
        __syncthreads();

        unsigned word = adjrow[jt];
#pragma unroll
        for (int kk = 0; kk < 16; kk++) {
            int k = kh + kk;
            float wv = 0.f;
            if ((word >> k) & 1u)
                wv = (tcol[k] > th_r) ? p_r * bcol[k] : q_r * dcol[k];
            w_s[k][r] = wv;
        }
        __syncthreads();

        if (n0 == 0 && tid < 128) {
#pragma unroll
            for (int k = 0; k < 32; k++) den += w_s[k][r];
        }
#pragma unroll 4
        for (int k = 0; k < 32; k++) {
            float4 w0 = *(float4*)&w_s[k][ty * 8];
            float4 w1 = *(float4*)&w_s[k][ty * 8 + 4];
            float4 hv = *(float4*)&h_s[k][tx * 4];
            float wr[8] = {w0.x, w0.y, w0.z, w0.w, w1.x, w1.y, w1.z, w1.w};
            float hc[4] = {hv.x, hv.y, hv.z, hv.w};
#pragma unroll
            for (int a = 0; a < 8; a++)
#pragma unroll
                for (int b = 0; b < 4; b++) acc[a][b] += wr[a] * hc[b];
        }
        __syncthreads();
    }

#pragma unroll
    for (int a = 0; a < 8; a++) {
        int row = i0 + ty * 8 + a;
        float4 o; o.x = acc[a][0]; o.y = acc[a][1]; o.z = acc[a][2]; o.w = acc[a][3];
        *(float4*)&g_num1[h][(long long)row * D1 + n0 + tx * 4] = o;
    }
    if (n0 == 0 && tid < 128) g_den1[h][i0 + r] = den;
}

// ---------------- 6. epilogue 1: heads -> z ----------------
__global__ void k_epi1(const float* __restrict__ head_b) {
    int i = blockIdx.x, c = threadIdx.x;   // 256 threads
    __shared__ float red[256];
    float o[2];
#pragma unroll
    for (int h = 0; h < 2; h++) {
        float v = g_num1[h][(long long)i * D1 + c] / g_den1[h][i];
        float e = eluf(v);
        red[c] = e * e;
        __syncthreads();
        for (int s = 128; s; s >>= 1) {
            if (c < s) red[c] += red[c + s];
            __syncthreads();
        }
        float nrm = sqrtf(red[0]);
        __syncthreads();
        o[h] = e / fmaxf(nrm, 1e-12f) + head_b[h * D1 + c];
    }
    float zm = 0.5f * (o[0] + o[1]);
    g_z[(long long)i * D1 + c] = eluf(zm);
}

// ---------------- 7. conv (1x129 valid) + s2,t2 ----------------
__global__ void k_conv(const float* __restrict__ conv_w, const float* __restrict__ conv_cb,
                       const float* __restrict__ conv_a) {
    int i = blockIdx.x, j = threadIdx.x;   // 128 threads
    __shared__ float zr[D1];
    __shared__ float wk[132];
    __shared__ float red[128];
    zr[j]       = g_z[(long long)i * D1 + j];
    zr[j + 128] = g_z[(long long)i * D1 + j + 128];
    wk[j] = conv_w[j];
    if (j == 0) wk[128] = conv_w[128];
    __syncthreads();
    float acc = conv_cb[0];
#pragma unroll 4
    for (int k = 0; k < 129; k++) acc += zr[j + k] * wk[k];
    g_hc[(long long)i * D2 + j] = acc;

    red[j] = acc * conv_a[j];
    __syncthreads();
    for (int s = 64; s; s >>= 1) {
        if (j < s) red[j] += red[j + s];
        __syncthreads();
    }
    if (j == 0) g_s2[i] = red[0];
    __syncthreads();
    red[j] = acc * conv_a[128 + j];
    __syncthreads();
    for (int s = 64; s; s >>= 1) {
        if (j < s) red[j] += red[j + s];
        __syncthreads();
    }
    if (j == 0) g_t2[i] = red[0];
}

// ---------------- 8. GAT2 per-node factors ----------------
__global__ void k_fac2() {
    __shared__ float red[1024];
    float m = -1e30f;
    for (int i = threadIdx.x; i < N_NODES; i += 1024) m = fmaxf(m, g_t2[i]);
    red[threadIdx.x] = m;
    __syncthreads();
    for (int s = 512; s; s >>= 1) {
        if (threadIdx.x < s) red[threadIdx.x] = fmaxf(red[threadIdx.x], red[threadIdx.x + s]);
        __syncthreads();
    }
    float tmax = red[0];
    for (int i = threadIdx.x; i < N_NODES; i += 1024) {
        float s_ = g_s2[i], t_ = g_t2[i];
        float v = s_ + tmax;
        float mm = v > 0.f ? v : (expf(v) - 1.f);    // elu(s+tmax) = row max
        g_P2[i]  = expf(v - mm);
        g_R2[i]  = expf(-1.f - mm);
        g_Es[i]  = expf(fminf(fmaxf(s_, -60.f), 60.f));
        g_B2[i]  = expf(t_ - tmax);
        g_Et[i]  = expf(fminf(fmaxf(t_, -60.f), 60.f));
        g_th2[i] = -s_;
    }
}

// ---------------- 9. GAT2 pass ----------------
__global__ __launch_bounds__(256) void k_gat2() {
    int i0 = blockIdx.x * 128, n0 = blockIdx.y * 64;

    __shared__ float w_s[32][128];
    __shared__ float h_s[32][64];
    __shared__ float Bcol[32], Ecol[32], tcol[32];

    int tid = threadIdx.x;
    int r = tid & 127, kh = (tid >> 7) * 16;
    float P_r  = g_P2[i0 + r];
    float R_r  = g_R2[i0 + r];
    float E_r  = g_Es[i0 + r];
    float th_r = g_th2[i0 + r];
    const unsigned* adjrow = g_adj + (long long)(i0 + r) * NW;

    int ty = tid >> 4, tx = tid & 15;
    float acc[8][4];
#pragma unroll
    for (int a = 0; a < 8; a++)
#pragma unroll
        for (int b = 0; b < 4; b++) acc[a][b] = 0.f;
    float den = 0.f;

    for (int jt = 0; jt < NW; jt++) {
        int j0 = jt * 32;
        if (tid < 32)       Bcol[tid]      = g_B2[j0 + tid];
        else if (tid < 64)  Ecol[tid - 32] = g_Et[j0 + tid - 32];
        else if (tid < 96)  tcol[tid - 64] = g_t2[j0 + tid - 64];
        {
            int k = tid >> 3, nq = (tid & 7) * 8;
            const float* hp = g_hc + (long long)(j0 + k) * D2 + n0 + nq;
            float4 v0 = *(const float4*)hp;
            float4 v1 = *(const float4*)(hp + 4);
            *(float4*)&h_s[k][nq] = v0;
            *(float4*)&h_s[k][nq + 4] = v1;
        }
        __syncthreads();

        unsigned word = adjrow[jt];
#pragma unroll
        for (int kk = 0; kk < 16; kk++) {
            int k = kh + kk;
            float wv = 0.f;
            if ((word >> k) & 1u) {
                if (tcol[k] > th_r) {
                    wv = P_r * Bcol[k];
                } else {
                    float g = E_r * Ecol[k];   // = exp(u) in (0,1]
                    // degree-8 Taylor of e^g on (0,1]
                    float eg = 1.f + g * (1.f + g * (0.5f + g * (0.16666667f +
                               g * (0.041666668f + g * (0.008333334f + g * (0.0013888889f +
                               g * (1.9841270e-4f + g * 2.4801587e-5f)))))));
                    wv = R_r * eg;
                }
            }
            w_s[k][r] = wv;
        }
        __syncthreads();

        if (n0 == 0 && tid < 128) {
#pragma unroll
            for (int k = 0; k < 32; k++) den += w_s[k][r];
        }
#pragma unroll 4
        for (int k = 0; k < 32; k++) {
            float4 w0 = *(float4*)&w_s[k][ty * 8];
            float4 w1 = *(float4*)&w_s[k][ty * 8 + 4];
            float4 hv = *(float4*)&h_s[k][tx * 4];
            float wr[8] = {w0.x, w0.y, w0.z, w0.w, w1.x, w1.y, w1.z, w1.w};
            float hc[4] = {hv.x, hv.y, hv.z, hv.w};
#pragma unroll
            for (int a = 0; a < 8; a++)
#pragma unroll
                for (int b = 0; b < 4; b++) acc[a][b] += wr[a] * hc[b];
        }
        __syncthreads();
    }

#pragma unroll
    for (int a = 0; a < 8; a++) {
        int row = i0 + ty * 8 + a;
        float4 o; o.x = acc[a][0]; o.y = acc[a][1]; o.z = acc[a][2]; o.w = acc[a][3];
        *(float4*)&g_num2[(long long)row * D2 + n0 + tx * 4] = o;
    }
    if (n0 == 0 && tid < 128) g_den2[i0 + r] = den;
}

// ---------------- 10. epilogue 2: embed ----------------
__global__ void k_epi2(const float* __restrict__ conv_b) {
    int i = blockIdx.x, c = threadIdx.x;   // 128 threads
    __shared__ float red[128];
    float v = g_num2[(long long)i * D2 + c] / g_den2[i];
    float e = eluf(v);
    red[c] = e * e;
    __syncthreads();
    for (int s = 64; s; s >>= 1) {
        if (c < s) red[c] += red[c + s];
        __syncthreads();
    }
    float nrm = sqrtf(red[0]);
    g_embed[(long long)i * D2 + c] = e / fmaxf(nrm, 1e-12f) + conv_b[c];
}

// ---------------- 11. pred ----------------
__global__ void k_pred(const int* __restrict__ ts, float* __restrict__ out) {
    int p = blockIdx.x * 8 + (threadIdx.x >> 5);
    if (p >= NPAIRS) return;
    int lane = threadIdx.x & 31;
    int i = ts[2 * p], j = ts[2 * p + 1];
    float a = g_tf[i * 64 + lane] * g_tg[j * 64 + lane]
            + g_tf[i * 64 + 32 + lane] * g_tg[j * 64 + 32 + lane];
#pragma unroll
    for (int o = 16; o; o >>= 1) a += __shfl_xor_sync(0xffffffffu, a, o);
    if (!lane) out[p] = a;
}

// ---------------- host launcher ----------------
extern "C" void kernel_launch(void* const* d_in, const int* in_sizes, int n_in,
                              void* d_out, int out_size) {
    const float* x        = (const float*)d_in[0];
    const int*   adj      = (const int*)d_in[1];
    const int*   tsamp    = (const int*)d_in[2];
    const float* head_W   = (const float*)d_in[3];
    const float* head_a   = (const float*)d_in[4];
    const float* head_b   = (const float*)d_in[5];
    const float* conv_w   = (const float*)d_in[6];
    const float* conv_cb  = (const float*)d_in[7];
    const float* conv_a   = (const float*)d_in[8];
    const float* conv_b   = (const float*)d_in[9];
    const float* tf_w1    = (const float*)d_in[10];
    const float* tf_b1    = (const float*)d_in[11];
    const float* tf_w2    = (const float*)d_in[12];
    const float* tf_b2    = (const float*)d_in[13];
    const float* tg_w1    = (const float*)d_in[14];
    const float* tg_b1    = (const float*)d_in[15];
    const float* tg_w2    = (const float*)d_in[16];
    const float* tg_b2    = (const float*)d_in[17];
    float* out = (float*)d_out;

    float *pH, *pEmbed, *pMid0, *pMid1, *pTf, *pTg;
    cudaGetSymbolAddress((void**)&pH, g_H);
    cudaGetSymbolAddress((void**)&pEmbed, g_embed);
    cudaGetSymbolAddress((void**)&pMid0, g_mid);
    pMid1 = pMid0 + (long long)N_NODES * D2;
    cudaGetSymbolAddress((void**)&pTf, g_tf);
    cudaGetSymbolAddress((void**)&pTg, g_tg);

    // 1. adjacency bit-pack
    k_pack<<<(N_NODES * NW) / 8, 256>>>(adj);

    // 2. h = x @ W per head
    k_gemm<0><<<dim3(N_NODES / 64, D1 / 64, NHEAD), 256>>>(
        x, head_W, nullptr, pH,
        N_NODES, INDIM, D1, 0LL, (long long)INDIM * D1, (long long)N_NODES * D1);

    // 3-4. s,t + factors
    k_st<<<dim3(N_NODES / 8, NHEAD), 256>>>(head_a);
    k_fac1<<<NHEAD, 1024>>>();

    // 5. GAT1
    k_gat1<<<dim3(N_NODES / 128, D1 / 64, NHEAD), 256>>>();

    // 6. z
    k_epi1<<<N_NODES, 256>>>(head_b);

    // 7. conv + s2,t2
    k_conv<<<N_NODES, 128>>>(conv_w, conv_cb, conv_a);

    // 8. factors 2
    k_fac2<<<1, 1024>>>();

    // 9. GAT2
    k_gat2<<<dim3(N_NODES / 128, D2 / 64), 256>>>();

    // 10. embed
    k_epi2<<<N_NODES, 128>>>(conv_b);

    // 11. MLPs
    k_gemm<1><<<dim3(N_NODES / 64, D2 / 64), 256>>>(
        pEmbed, tf_w1, tf_b1, pMid0, N_NODES, D2, D2, 0LL, 0LL, 0LL);
    k_gemm<1><<<dim3(N_NODES / 64, 1), 256>>>(
        pMid0, tf_w2, tf_b2, pTf, N_NODES, D2, 64, 0LL, 0LL, 0LL);
    k_gemm<1><<<dim3(N_NODES / 64, D2 / 64), 256>>>(
        pEmbed, tg_w1, tg_b1, pMid1, N_NODES, D2, D2, 0LL, 0LL, 0LL);
    k_gemm<1><<<dim3(N_NODES / 64, 1), 256>>>(
        pMid1, tg_w2, tg_b2, pTg, N_NODES, D2, 64, 0LL, 0LL, 0LL);

    // 12. predictions
    k_pred<<<(NPAIRS + 7) / 8, 256>>>(tsamp, out);
}

// round 5
// speedup vs baseline: 1.0009x; 1.0009x over previous
#include <cuda_runtime.h>
#include <math.h>

#define N_NODES 8192
#define INDIM   768
#define D1      256
#define D2      128
#define NHEAD   2
#define ALPHAF  0.2f
#define NPAIRS  100000
#define NW      (N_NODES/32)   // 256 adjacency words per row

// ---------------- static device scratch (no allocation) ----------------
__device__ unsigned g_adj[N_NODES * NW];

__device__ float g_H[NHEAD][N_NODES * D1];
__device__ float g_s1[NHEAD][N_NODES], g_t1[NHEAD][N_NODES];
__device__ float g_p1[NHEAD][N_NODES], g_q1[NHEAD][N_NODES];
__device__ float g_b1[NHEAD][N_NODES], g_d1[NHEAD][N_NODES];
__device__ float g_th1[NHEAD][N_NODES];
__device__ float g_num1[NHEAD][N_NODES * D1];
__device__ float g_den1[NHEAD][N_NODES];

__device__ float g_z[N_NODES * D1];
__device__ float g_hc[N_NODES * D2];
__device__ float g_s2[N_NODES], g_t2[N_NODES];
__device__ float g_P2[N_NODES], g_R2[N_NODES], g_Es[N_NODES];
__device__ float g_B2[N_NODES], g_Et[N_NODES], g_th2[N_NODES];
__device__ float g_num2[N_NODES * D2];
__device__ float g_den2[N_NODES];
__device__ float g_embed[N_NODES * D2];

__device__ float g_mid[2][N_NODES * D2];
__device__ float g_tf[N_NODES * 64];
__device__ float g_tg[N_NODES * 64];

__device__ __forceinline__ float eluf(float x) { return x > 0.f ? x : (expf(x) - 1.f); }

// ---------------- 1. pack adjacency into bits ----------------
__global__ void k_pack(const int* __restrict__ adj) {
    int w = blockIdx.x * 8 + (threadIdx.x >> 5);       // word id
    int lane = threadIdx.x & 31;
    int e = w * 32 + lane;                             // element id (< 2^26)
    int v = adj[e];
    unsigned m = __ballot_sync(0xffffffffu, v > 0);
    if (lane == 0) g_adj[w] = m;
}

// ---------------- 2. generic fp32 GEMM: C = act(A@W + bias) ----------------
// BM=64, BN=64, BK=32, 256 threads, 4x4 micro-tile. M%64==0, K%32==0, N%64==0.
template <int ACT>
__global__ __launch_bounds__(256) void k_gemm(
    const float* __restrict__ A, const float* __restrict__ W,
    const float* __restrict__ bias, float* __restrict__ C,
    int M, int K, int N, long long astride, long long wstride, long long cstride)
{
    const float* Az = A + (long long)blockIdx.z * astride;
    const float* Wz = W + (long long)blockIdx.z * wstride;
    float*       Cz = C + (long long)blockIdx.z * cstride;

    __shared__ float a_s[32][65];
    __shared__ float w_s[32][64];

    int m0 = blockIdx.x * 64, n0 = blockIdx.y * 64;
    int tid = threadIdx.x;
    int ty = tid >> 4, tx = tid & 15;

    float acc[4][4];
#pragma unroll
    for (int r = 0; r < 4; r++)
#pragma unroll
        for (int c = 0; c < 4; c++) acc[r][c] = 0.f;

    for (int k0 = 0; k0 < K; k0 += 32) {
        {   // A tile -> transposed smem
            int m = tid & 63, kq = (tid >> 6) * 8;
            const float* ap = Az + (long long)(m0 + m) * K + k0 + kq;
            float4 v0 = *(const float4*)ap;
            float4 v1 = *(const float4*)(ap + 4);
            a_s[kq + 0][m] = v0.x; a_s[kq + 1][m] = v0.y;
            a_s[kq + 2][m] = v0.z; a_s[kq + 3][m] = v0.w;
            a_s[kq + 4][m] = v1.x; a_s[kq + 5][m] = v1.y;
            a_s[kq + 6][m] = v1.z; a_s[kq + 7][m] = v1.w;
        }
        {   // W tile
            int k = tid >> 3, nq = (tid & 7) * 8;
            const float* wp = Wz + (long long)(k0 + k) * N + n0 + nq;
            float4 v0 = *(const float4*)wp;
            float4 v1 = *(const float4*)(wp + 4);
            *(float4*)&w_s[k][nq] = v0;
            *(float4*)&w_s[k][nq + 4] = v1;
        }
        __syncthreads();
#pragma unroll 8
        for (int k = 0; k < 32; k++) {
            float av[4];
#pragma unroll
            for (int r = 0; r < 4; r++) av[r] = a_s[k][ty * 4 + r];
            float4 wv = *(float4*)&w_s[k][tx * 4];
            float bv[4] = {wv.x, wv.y, wv.z, wv.w};
#pragma unroll
            for (int r = 0; r < 4; r++)
#pragma unroll
                for (int c = 0; c < 4; c++) acc[r][c] += av[r] * bv[c];
        }
        __syncthreads();
    }

    float bb[4] = {0.f, 0.f, 0.f, 0.f};
    if (bias) {
#pragma unroll
        for (int c = 0; c < 4; c++) bb[c] = bias[n0 + tx * 4 + c];
    }
#pragma unroll
    for (int r = 0; r < 4; r++) {
        int row = m0 + ty * 4 + r;
        float4 o;
        float v0 = acc[r][0] + bb[0], v1 = acc[r][1] + bb[1];
        float v2 = acc[r][2] + bb[2], v3 = acc[r][3] + bb[3];
        if (ACT == 1) { v0 = eluf(v0); v1 = eluf(v1); v2 = eluf(v2); v3 = eluf(v3); }
        o.x = v0; o.y = v1; o.z = v2; o.w = v3;
        *(float4*)&Cz[(long long)row * N + n0 + tx * 4] = o;
    }
}

// ---------------- 3. s,t per node per head ----------------
__global__ void k_st(const float* __restrict__ head_a) {
    int h = blockIdx.y;
    int warp = threadIdx.x >> 5, lane = threadIdx.x & 31;
    int i = blockIdx.x * 8 + warp;
    const float* H = g_H[h] + (long long)i * D1;
    const float* ah = head_a + h * 2 * D1;
    float s = 0.f, t = 0.f;
#pragma unroll
    for (int d = lane; d < D1; d += 32) {
        float hv = H[d];
        s += hv * ah[d];
        t += hv * ah[D1 + d];
    }
#pragma unroll
    for (int o = 16; o; o >>= 1) {
        s += __shfl_xor_sync(0xffffffffu, s, o);
        t += __shfl_xor_sync(0xffffffffu, t, o);
    }
    if (!lane) { g_s1[h][i] = s; g_t1[h][i] = t; }
}

// ---------------- 4. GAT1 per-node softmax factors ----------------
__global__ void k_fac1() {
    int h = blockIdx.x;
    __shared__ float red[1024];
    float m = -1e30f;
    for (int i = threadIdx.x; i < N_NODES; i += 1024) m = fmaxf(m, g_t1[h][i]);
    red[threadIdx.x] = m;
    __syncthreads();
    for (int s = 512; s; s >>= 1) {
        if (threadIdx.x < s) red[threadIdx.x] = fmaxf(red[threadIdx.x], red[threadIdx.x + s]);
        __syncthreads();
    }
    float tmax = red[0];
    for (int i = threadIdx.x; i < N_NODES; i += 1024) {
        float s_ = g_s1[h][i], t_ = g_t1[h][i];
        float v = s_ + tmax;
        float mm = v > 0.f ? v : ALPHAF * v;     // lrelu(s+tmax) = row max
        g_p1[h][i]  = expf(v - mm);              // <= 1
        g_q1[h][i]  = expf(ALPHAF * v - mm);     // <= 1
        g_b1[h][i]  = expf(t_ - tmax);           // <= 1
        g_d1[h][i]  = expf(ALPHAF * (t_ - tmax));
        g_th1[h][i] = -s_;
    }
}

// ---------------- 5. GAT1 pass: num = W.h, den = W.1 ----------------
// BM=128 rows, BN=64 cols of D1, BK=32 (one adj word). 256 thr, 8x4 micro.
__global__ __launch_bounds__(256) void k_gat1() {
    int h = blockIdx.z;
    int i0 = blockIdx.x * 128, n0 = blockIdx.y * 64;

    __shared__ float w_s[32][128];
    __shared__ float h_s[32][64];
    __shared__ float bcol[32], dcol[32], tcol[32];

    int tid = threadIdx.x;
    int r = tid & 127, kh = (tid >> 7) * 16;
    float p_r  = g_p1[h][i0 + r];
    float q_r  = g_q1[h][i0 + r];
    float th_r = g_th1[h][i0 + r];
    const unsigned* adjrow = g_adj + (long long)(i0 + r) * NW;

    int ty = tid >> 4, tx = tid & 15;
    float acc[8][4];
#pragma unroll
    for (int a = 0; a < 8; a++)
#pragma unroll
        for (int b = 0; b < 4; b++) acc[a][b] = 0.f;
    float den = 0.f;
    const float* Hh = g_H[h];

    for (int jt = 0; jt < NW; jt++) {
        int j0 = jt * 32;
        if (tid < 32)       bcol[tid]      = g_b1[h][j0 + tid];
        else if (tid < 64)  dcol[tid - 32] = g_d1[h][j0 + tid - 32];
        else if (tid < 96)  tcol[tid - 64] = g_t1[h][j0 + tid - 64];
        {
            int k = tid >> 3, nq = (tid & 7) * 8;
            const float* hp = Hh + (long long)(j0 + k) * D1 + n0 + nq;
            float4 v0 = *(const float4*)hp;
            float4 v1 = *(const float4*)(hp + 4);
            *(float4*)&h_s[k][nq] = v0;
            *(float4*)&h_s[k][nq + 4] = v1;
        }
        __syncthreads();

        unsigned word = adjrow[jt];
#pragma unroll
        for (int kk = 0; kk < 16; kk++) {
            int k = kh + kk;
            float wv = 0.f;
            if ((word >> k) & 1u)
                wv = (tcol[k] > th_r) ? p_r * bcol[k] : q_r * dcol[k];
            w_s[k][r] = wv;
        }
        __syncthreads();

        if (n0 == 0 && tid < 128) {
#pragma unroll
            for (int k = 0; k < 32; k++) den += w_s[k][r];
        }
#pragma unroll 4
        for (int k = 0; k < 32; k++) {
            float4 w0 = *(float4*)&w_s[k][ty * 8];
            float4 w1 = *(float4*)&w_s[k][ty * 8 + 4];
            float4 hv = *(float4*)&h_s[k][tx * 4];
            float wr[8] = {w0.x, w0.y, w0.z, w0.w, w1.x, w1.y, w1.z, w1.w};
            float hc[4] = {hv.x, hv.y, hv.z, hv.w};
#pragma unroll
            for (int a = 0; a < 8; a++)
#pragma unroll
                for (int b = 0; b < 4; b++) acc[a][b] += wr[a] * hc[b];
        }
        __syncthreads();
    }

#pragma unroll
    for (int a = 0; a < 8; a++) {
        int row = i0 + ty * 8 + a;
        float4 o; o.x = acc[a][0]; o.y = acc[a][1]; o.z = acc[a][2]; o.w = acc[a][3];
        *(float4*)&g_num1[h][(long long)row * D1 + n0 + tx * 4] = o;
    }
    if (n0 == 0 && tid < 128) g_den1[h][i0 + r] = den;
}

// ---------------- 6. epilogue 1: heads -> z ----------------
__global__ void k_epi1(const float* __restrict__ head_b) {
    int i = blockIdx.x, c = threadIdx.x;   // 256 threads
    __shared__ float red[256];
    float o[2];
#pragma unroll
    for (int h = 0; h < 2; h++) {
        float v = g_num1[h][(long long)i * D1 + c] / g_den1[h][i];
        float e = eluf(v);
        red[c] = e * e;
        __syncthreads();
        for (int s = 128; s; s >>= 1) {
            if (c < s) red[c] += red[c + s];
            __syncthreads();
        }
        float nrm = sqrtf(red[0]);
        __syncthreads();
        o[h] = e / fmaxf(nrm, 1e-12f) + head_b[h * D1 + c];
    }
    float zm = 0.5f * (o[0] + o[1]);
    g_z[(long long)i * D1 + c] = eluf(zm);
}

// ---------------- 7. conv (1x129 valid) + s2,t2 ----------------
__global__ void k_conv(const float* __restrict__ conv_w, const float* __restrict__ conv_cb,
                       const float* __restrict__ conv_a) {
    int i = blockIdx.x, j = threadIdx.x;   // 128 threads
    __shared__ float zr[D1];
    __shared__ float wk[132];
    __shared__ float red[128];
    zr[j]       = g_z[(long long)i * D1 + j];
    zr[j + 128] = g_z[(long long)i * D1 + j + 128];
    wk[j] = conv_w[j];
    if (j == 0) wk[128] = conv_w[128];
    __syncthreads();
    float acc = conv_cb[0];
#pragma unroll 4
    for (int k = 0; k < 129; k++) acc += zr[j + k] * wk[k];
    g_hc[(long long)i * D2 + j] = acc;

    red[j] = acc * conv_a[j];
    __syncthreads();
    for (int s = 64; s; s >>= 1) {
        if (j < s) red[j] += red[j + s];
        __syncthreads();
    }
    if (j == 0) g_s2[i] = red[0];
    __syncthreads();
    red[j] = acc * conv_a[128 + j];
    __syncthreads();
    for (int s = 64; s; s >>= 1) {
        if (j < s) red[j] += red[j + s];
        __syncthreads();
    }
    if (j == 0) g_t2[i] = red[0];
}

// ---------------- 8. GAT2 per-node factors ----------------
__global__ void k_fac2() {
    __shared__ float red[1024];
    float m = -1e30f;
    for (int i = threadIdx.x; i < N_NODES; i += 1024) m = fmaxf(m, g_t2[i]);
    red[threadIdx.x] = m;
    __syncthreads();
    for (int s = 512; s; s >>= 1) {
        if (threadIdx.x < s) red[threadIdx.x] = fmaxf(red[threadIdx.x], red[threadIdx.x + s]);
        __syncthreads();
    }
    float tmax = red[0];
    for (int i = threadIdx.x; i < N_NODES; i += 1024) {
        float s_ = g_s2[i], t_ = g_t2[i];
        float v = s_ + tmax;
        float mm = v > 0.f ? v : (expf(v) - 1.f);    // elu(s+tmax) = row max
        g_P2[i]  = expf(v - mm);
        g_R2[i]  = expf(-1.f - mm);
        g_Es[i]  = expf(fminf(fmaxf(s_, -60.f), 60.f));
        g_B2[i]  = expf(t_ - tmax);
        g_Et[i]  = expf(fminf(fmaxf(t_, -60.f), 60.f));
        g_th2[i] = -s_;
    }
}

// ---------------- 9. GAT2 pass ----------------
__global__ __launch_bounds__(256) void k_gat2() {
    int i0 = blockIdx.x * 128, n0 = blockIdx.y * 64;

    __shared__ float w_s[32][128];
    __shared__ float h_s[32][64];
    __shared__ float Bcol[32], Ecol[32], tcol[32];

    int tid = threadIdx.x;
    int r = tid & 127, kh = (tid >> 7) * 16;
    float P_r  = g_P2[i0 + r];
    float R_r  = g_R2[i0 + r];
    float E_r  = g_Es[i0 + r];
    float th_r = g_th2[i0 + r];
    const unsigned* adjrow = g_adj + (long long)(i0 + r) * NW;

    int ty = tid >> 4, tx = tid & 15;
    float acc[8][4];
#pragma unroll
    for (int a = 0; a < 8; a++)
#pragma unroll
        for (int b = 0; b < 4; b++) acc[a][b] = 0.f;
    float den = 0.f;

    for (int jt = 0; jt < NW; jt++) {
        int j0 = jt * 32;
        if (tid < 32)       Bcol[tid]      = g_B2[j0 + tid];
        else if (tid < 64)  Ecol[tid - 32] = g_Et[j0 + tid - 32];
        else if (tid < 96)  tcol[tid - 64] = g_t2[j0 + tid - 64];
        {
            int k = tid >> 3, nq = (tid & 7) * 8;
            const float* hp = g_hc + (long long)(j0 + k) * D2 + n0 + nq;
            float4 v0 = *(const float4*)hp;
            float4 v1 = *(const float4*)(hp + 4);
            *(float4*)&h_s[k][nq] = v0;
            *(float4*)&h_s[k][nq + 4] = v1;
        }
        __syncthreads();

        unsigned word = adjrow[jt];
#pragma unroll
        for (int kk = 0; kk < 16; kk++) {
            int k = kh + kk;
            float wv = 0.f;
            if ((word >> k) & 1u) {
                if (tcol[k] > th_r) {
                    wv = P_r * Bcol[k];
                } else {
                    float g = E_r * Ecol[k];   // = exp(u) in (0,1]
                    // degree-8 Taylor of e^g on (0,1]
                    float eg = 1.f + g * (1.f + g * (0.5f + g * (0.16666667f +
                               g * (0.041666668f + g * (0.008333334f + g * (0.0013888889f +
                               g * (1.9841270e-4f + g * 2.4801587e-5f)))))));
                    wv = R_r * eg;
                }
            }
            w_s[k][r] = wv;
        }
        __syncthreads();

        if (n0 == 0 && tid < 128) {
#pragma unroll
            for (int k = 0; k < 32; k++) den += w_s[k][r];
        }
#pragma unroll 4
        for (int k = 0; k < 32; k++) {
            float4 w0 = *(float4*)&w_s[k][ty * 8];
            float4 w1 = *(float4*)&w_s[k][ty * 8 + 4];
            float4 hv = *(float4*)&h_s[k][tx * 4];
            float wr[8] = {w0.x, w0.y, w0.z, w0.w, w1.x, w1.y, w1.z, w1.w};
            float hc[4] = {hv.x, hv.y, hv.z, hv.w};
#pragma unroll
            for (int a = 0; a < 8; a++)
#pragma unroll
                for (int b = 0; b < 4; b++) acc[a][b] += wr[a] * hc[b];
        }
        __syncthreads();
    }

#pragma unroll
    for (int a = 0; a < 8; a++) {
        int row = i0 + ty * 8 + a;
        float4 o; o.x = acc[a][0]; o.y = acc[a][1]; o.z = acc[a][2]; o.w = acc[a][3];
        *(float4*)&g_num2[(long long)row * D2 + n0 + tx * 4] = o;
    }
    if (n0 == 0 && tid < 128) g_den2[i0 + r] = den;
}

// ---------------- 10. epilogue 2: embed ----------------
__global__ void k_epi2(const float* __restrict__ conv_b) {
    int i = blockIdx.x, c = threadIdx.x;   // 128 threads
    __shared__ float red[128];
    float v = g_num2[(long long)i * D2 + c] / g_den2[i];
    float e = eluf(v);
    red[c] = e * e;
    __syncthreads();
    for (int s = 64; s; s >>= 1) {
        if (c < s) red[c] += red[c + s];
        __syncthreads();
    }
    float nrm = sqrtf(red[0]);
    g_embed[(long long)i * D2 + c] = e / fmaxf(nrm, 1e-12f) + conv_b[c];
}

// ---------------- 11. pred ----------------
__global__ void k_pred(const int* __restrict__ ts, float* __restrict__ out) {
    int p = blockIdx.x * 8 + (threadIdx.x >> 5);
    if (p >= NPAIRS) return;
    int lane = threadIdx.x & 31;
    int i = ts[2 * p], j = ts[2 * p + 1];
    float a = g_tf[i * 64 + lane] * g_tg[j * 64 + lane]
            + g_tf[i * 64 + 32 + lane] * g_tg[j * 64 + 32 + lane];
#pragma unroll
    for (int o = 16; o; o >>= 1) a += __shfl_xor_sync(0xffffffffu, a, o);
    if (!lane) out[p] = a;
}

// ---------------- host launcher ----------------
extern "C" void kernel_launch(void* const* d_in, const int* in_sizes, int n_in,
                              void* d_out, int out_size) {
    const float* x        = (const float*)d_in[0];
    const int*   adj      = (const int*)d_in[1];
    const int*   tsamp    = (const int*)d_in[2];
    const float* head_W   = (const float*)d_in[3];
    const float* head_a   = (const float*)d_in[4];
    const float* head_b   = (const float*)d_in[5];
    const float* conv_w   = (const float*)d_in[6];
    const float* conv_cb  = (const float*)d_in[7];
    const float* conv_a   = (const float*)d_in[8];
    const float* conv_b   = (const float*)d_in[9];
    const float* tf_w1    = (const float*)d_in[10];
    const float* tf_b1    = (const float*)d_in[11];
    const float* tf_w2    = (const float*)d_in[12];
    const float* tf_b2    = (const float*)d_in[13];
    const float* tg_w1    = (const float*)d_in[14];
    const float* tg_b1    = (const float*)d_in[15];
    const float* tg_w2    = (const float*)d_in[16];
    const float* tg_b2    = (const float*)d_in[17];
    float* out = (float*)d_out;

    float *pH, *pEmbed, *pMid0, *pMid1, *pTf, *pTg;
    cudaGetSymbolAddress((void**)&pH, g_H);
    cudaGetSymbolAddress((void**)&pEmbed, g_embed);
    cudaGetSymbolAddress((void**)&pMid0, g_mid);
    pMid1 = pMid0 + (long long)N_NODES * D2;
    cudaGetSymbolAddress((void**)&pTf, g_tf);
    cudaGetSymbolAddress((void**)&pTg, g_tg);

    // 1. adjacency bit-pack
    k_pack<<<(N_NODES * NW) / 8, 256>>>(adj);

    // 2. h = x @ W per head
    k_gemm<0><<<dim3(N_NODES / 64, D1 / 64, NHEAD), 256>>>(
        x, head_W, nullptr, pH,
        N_NODES, INDIM, D1, 0LL, (long long)INDIM * D1, (long long)N_NODES * D1);

    // 3-4. s,t + factors
    k_st<<<dim3(N_NODES / 8, NHEAD), 256>>>(head_a);
    k_fac1<<<NHEAD, 1024>>>();

    // 5. GAT1
    k_gat1<<<dim3(N_NODES / 128, D1 / 64, NHEAD), 256>>>();

    // 6. z
    k_epi1<<<N_NODES, 256>>>(head_b);

    // 7. conv + s2,t2
    k_conv<<<N_NODES, 128>>>(conv_w, conv_cb, conv_a);

    // 8. factors 2
    k_fac2<<<1, 1024>>>();

    // 9. GAT2
    k_gat2<<<dim3(N_NODES / 128, D2 / 64), 256>>>();

    // 10. embed
    k_epi2<<<N_NODES, 128>>>(conv_b);

    // 11. MLPs
    k_gemm<1><<<dim3(N_NODES / 64, D2 / 64), 256>>>(
        pEmbed, tf_w1, tf_b1, pMid0, N_NODES, D2, D2, 0LL, 0LL, 0LL);
    k_gemm<1><<<dim3(N_NODES / 64, 1), 256>>>(
        pMid0, tf_w2, tf_b2, pTf, N_NODES, D2, 64, 0LL, 0LL, 0LL);
    k_gemm<1><<<dim3(N_NODES / 64, D2 / 64), 256>>>(
        pEmbed, tg_w1, tg_b1, pMid1, N_NODES, D2, D2, 0LL, 0LL, 0LL);
    k_gemm<1><<<dim3(N_NODES / 64, 1), 256>>>(
        pMid1, tg_w2, tg_b2, pTg, N_NODES, D2, 64, 0LL, 0LL, 0LL);

    // 12. predictions
    k_pred<<<(NPAIRS + 7) / 8, 256>>>(tsamp, out);
}

// round 12
// speedup vs baseline: 1.9336x; 1.9318x over previous
#include <cuda_runtime.h>
#include <cuda_bf16.h>
#include <cstdint>
#include <math.h>

#define N_NODES 8192
#define INDIM   768
#define D1      256
#define D2      128
#define NHEAD   2
#define ALPHAF  0.2f
#define NPAIRS  100000
#define NW      (N_NODES/32)

__device__ unsigned g_adj[N_NODES * NW];
__device__ float g_H[NHEAD][N_NODES * D1];
__device__ float g_s1[NHEAD][N_NODES], g_t1[NHEAD][N_NODES];
__device__ float g_p1[NHEAD][N_NODES], g_q1[NHEAD][N_NODES], g_th1[NHEAD][N_NODES];
__device__ float g_b1[NHEAD][N_NODES], g_d1[NHEAD][N_NODES];
__device__ float g_num1[NHEAD][N_NODES * D1];
__device__ float g_den1[NHEAD][N_NODES];
__device__ float g_z[N_NODES * D1];
__device__ float g_hc[N_NODES * D2];
__device__ float g_s2[N_NODES], g_t2[N_NODES];
__device__ float g_P2[N_NODES], g_R2[N_NODES], g_Es[N_NODES], g_th2[N_NODES];
__device__ float g_B2[N_NODES], g_Et[N_NODES];
__device__ float g_num2[N_NODES * D2];
__device__ float g_den2[N_NODES];
__device__ float g_embed[N_NODES * D2];
__device__ float g_mid[2][N_NODES * D2];
__device__ float g_tf[N_NODES * 64];
__device__ float g_tg[N_NODES * 64];

__device__ __forceinline__ float eluf(float x) { return x > 0.f ? x : (expf(x) - 1.f); }
__device__ __forceinline__ uint32_t smem_u32(const void* p) {
    uint32_t a;
    asm("{ .reg .u64 t; cvta.to.shared.u64 t, %1; cvt.u32.u64 %0, t; }" : "=r"(a) : "l"(p));
    return a;
}
__device__ __forceinline__ void ldsm4(unsigned* f, uint32_t addr) {
    asm volatile("ldmatrix.sync.aligned.m8n8.x4.shared.b16 {%0,%1,%2,%3}, [%4];"
                 : "=r"(f[0]), "=r"(f[1]), "=r"(f[2]), "=r"(f[3]) : "r"(addr));
}
__device__ __forceinline__ void ldsm4t(unsigned* f, uint32_t addr) {
    asm volatile("ldmatrix.sync.aligned.m8n8.x4.trans.shared.b16 {%0,%1,%2,%3}, [%4];"
                 : "=r"(f[0]), "=r"(f[1]), "=r"(f[2]), "=r"(f[3]) : "r"(addr));
}
__device__ __forceinline__ void mma16816(float* c, const unsigned* a, unsigned b0, unsigned b1) {
    asm volatile("mma.sync.aligned.m16n8k16.row.col.f32.bf16.bf16.f32 "
                 "{%0,%1,%2,%3}, {%4,%5,%6,%7}, {%8,%9}, {%0,%1,%2,%3};"
                 : "+f"(c[0]), "+f"(c[1]), "+f"(c[2]), "+f"(c[3])
                 : "r"(a[0]), "r"(a[1]), "r"(a[2]), "r"(a[3]), "r"(b0), "r"(b1));
}
// split (a,b) -> bf16 hi pair + bf16 lo (residual) pair
__device__ __forceinline__ void sp2(float a, float b, unsigned& h, unsigned& l) {
    __nv_bfloat162 hb = __floats2bfloat162_rn(a, b);
    __nv_bfloat162 lb = __floats2bfloat162_rn(a - __bfloat162float(hb.x),
                                              b - __bfloat162float(hb.y));
    h = *reinterpret_cast<unsigned*>(&hb);
    l = *reinterpret_cast<unsigned*>(&lb);
}

__global__ void k_pack(const int* __restrict__ adj) {
    int w = blockIdx.x * 8 + (threadIdx.x >> 5);
    int lane = threadIdx.x & 31;
    unsigned m = __ballot_sync(0xffffffffu, adj[w * 32 + lane] > 0);
    if (lane == 0) g_adj[w] = m;
}

// MODE 0: g_H = x @ head_W ; MODE 1: GAT1 num/den ; MODE 2: GAT2 num/den
// Split-precision bf16 MMA: every tile stored as hi+lo, 3-term products.
// grid (M/128, DTOT/128, z), 256 thr = 8 warps (2m x 4n), warp tile 64x32.
template <int MODE>
__global__ __launch_bounds__(256) void k_mma(const float* __restrict__ Ax,
                                             const float* __restrict__ Bw) {
    constexpr int NCH  = (MODE == 0) ? (INDIM / 128) : (N_NODES / 128);
    constexpr int DTOT = (MODE == 2) ? D2 : D1;
    constexpr int ST = 136;

    extern __shared__ char smem[];
    float* s_f0 = (float*)smem;
    float* s_f1 = (float*)(smem + 512);
    float* s_t  = (float*)(smem + 1024);
    float* s_dn = (float*)(smem + 1536);
    __nv_bfloat16* a_hi = (__nv_bfloat16*)(smem + 4096);
    __nv_bfloat16* a_lo = (__nv_bfloat16*)(smem + 38912);
    __nv_bfloat16* b_hi = (__nv_bfloat16*)(smem + 73728);
    __nv_bfloat16* b_lo = (__nv_bfloat16*)(smem + 108544);
    uint32_t uah = smem_u32(a_hi), ual = smem_u32(a_lo);
    uint32_t ubh = smem_u32(b_hi), ubl = smem_u32(b_lo);

    int tid = threadIdx.x, wid = tid >> 5, lane = tid & 31;
    int i0 = blockIdx.x * 128, n0 = blockIdx.y * 128, z = blockIdx.z;
    int warp_m = wid >> 2, warp_n = wid & 3;
    int r = tid & 127, half = tid >> 7;

    float rf0 = 0.f, rf1 = 0.f, rf2 = 0.f, rth = 0.f, den = 0.f;
    const unsigned* adjrow = nullptr;
    if (MODE == 1) {
        rf0 = g_p1[z][i0 + r]; rf1 = g_q1[z][i0 + r]; rth = g_th1[z][i0 + r];
        adjrow = g_adj + (size_t)(i0 + r) * NW;
    } else if (MODE == 2) {
        rf0 = g_P2[i0 + r]; rf1 = g_R2[i0 + r]; rf2 = g_Es[i0 + r]; rth = g_th2[i0 + r];
        adjrow = g_adj + (size_t)(i0 + r) * NW;
    }
    const float* Bs = (MODE == 0) ? Bw + (size_t)z * INDIM * D1
                                  : (MODE == 1 ? g_H[z] : g_hc);

    float acc[4][4][4];
#pragma unroll
    for (int a = 0; a < 4; a++)
#pragma unroll
        for (int b = 0; b < 4; b++)
#pragma unroll
            for (int c = 0; c < 4; c++) acc[a][b][c] = 0.f;

    for (int jc = 0; jc < NCH; ++jc) {
        int j0 = jc * 128;
        __syncthreads();
        if (MODE >= 1 && tid < 128) {
            s_f0[tid] = (MODE == 1) ? g_b1[z][j0 + tid] : g_B2[j0 + tid];
            s_f1[tid] = (MODE == 1) ? g_d1[z][j0 + tid] : g_Et[j0 + tid];
            s_t[tid]  = (MODE == 1) ? g_t1[z][j0 + tid] : g_t2[j0 + tid];
        }
        if (MODE >= 1) __syncthreads();
        // B tile (fp32 src) -> hi/lo bf16
#pragma unroll
        for (int it = 0; it < 8; ++it) {
            int idx = it * 256 + tid, row = idx >> 4, q = idx & 15;
            const float* p = Bs + (size_t)(j0 + row) * DTOT + n0 + q * 8;
            float4 v0 = *(const float4*)p, v1 = *(const float4*)(p + 4);
            uint4 h, l;
            sp2(v0.x, v0.y, h.x, l.x); sp2(v0.z, v0.w, h.y, l.y);
            sp2(v1.x, v1.y, h.z, l.z); sp2(v1.z, v1.w, h.w, l.w);
            *(uint4*)(b_hi + row * ST + q * 8) = h;
            *(uint4*)(b_lo + row * ST + q * 8) = l;
        }
        // A tile
        if (MODE == 0) {
            const float* ap = Ax + (size_t)(i0 + r) * INDIM + j0 + half * 64;
#pragma unroll
            for (int seg = 0; seg < 8; ++seg) {
                float4 v0 = *(const float4*)(ap + seg * 8);
                float4 v1 = *(const float4*)(ap + seg * 8 + 4);
                uint4 h, l;
                sp2(v0.x, v0.y, h.x, l.x); sp2(v0.z, v0.w, h.y, l.y);
                sp2(v1.x, v1.y, h.z, l.z); sp2(v1.z, v1.w, h.w, l.w);
                *(uint4*)(a_hi + r * ST + half * 64 + seg * 8) = h;
                *(uint4*)(a_lo + r * ST + half * 64 + seg * 8) = l;
            }
        } else {
            unsigned w0 = adjrow[jc * 4 + half * 2];
            unsigned w1 = adjrow[jc * 4 + half * 2 + 1];
            const float* f0p = s_f0 + half * 64;
            const float* f1p = s_f1 + half * 64;
            const float* tp  = s_t  + half * 64;
#pragma unroll
            for (int seg = 0; seg < 8; ++seg) {
                unsigned word = (seg < 4) ? w0 : w1;
                float f[8];
#pragma unroll
                for (int e = 0; e < 8; ++e) {
                    int jj = seg * 8 + e;
                    float w = 0.f;
                    if ((word >> (jj & 31)) & 1u) {
                        float b = f0p[jj], d = f1p[jj], t = tp[jj];
                        if (MODE == 1) {
                            w = (t > rth) ? rf0 * b : rf1 * d;
                        } else {
                            if (t > rth) w = rf0 * b;
                            else {
                                float g = rf2 * d;   // exp(s+t) in (0,1]
                                float eg = 1.f + g * (1.f + g * (0.5f + g * (0.16666667f +
                                           g * (0.041666668f + g * (0.008333334f + g * (0.0013888889f +
                                           g * (1.9841270e-4f + g * 2.4801587e-5f)))))));
                                w = rf1 * eg;
                            }
                        }
                    }
                    den += w;
                    f[e] = w;
                }
                uint4 h, l;
                sp2(f[0], f[1], h.x, l.x); sp2(f[2], f[3], h.y, l.y);
                sp2(f[4], f[5], h.z, l.z); sp2(f[6], f[7], h.w, l.w);
                *(uint4*)(a_hi + r * ST + half * 64 + seg * 8) = h;
                *(uint4*)(a_lo + r * ST + half * 64 + seg * 8) = l;
            }
        }
        __syncthreads();
        // 3-term split MMA over the 128x128x128 chunk
#pragma unroll
        for (int ks = 0; ks < 8; ++ks) {
            unsigned bh[2][4], bl[2][4];
#pragma unroll
            for (int np = 0; np < 2; ++np) {
                uint32_t off = (uint32_t)(((ks * 16 + (lane & 15)) * ST
                               + warp_n * 32 + np * 16 + (lane >> 4) * 8) * 2);
                ldsm4t(bh[np], ubh + off);
                ldsm4t(bl[np], ubl + off);
            }
#pragma unroll
            for (int mt = 0; mt < 4; ++mt) {
                uint32_t aoff = (uint32_t)(((warp_m * 64 + mt * 16 + (lane & 15)) * ST
                                + ks * 16 + (lane >> 4) * 8) * 2);
                unsigned ah[4], al[4];
                ldsm4(ah, uah + aoff);
                ldsm4(al, ual + aoff);
#pragma unroll
                for (int nt = 0; nt < 4; ++nt) {
                    const unsigned* bp = bh[nt >> 1];
                    const unsigned* lp = bl[nt >> 1];
                    int o = (nt & 1) * 2;
                    mma16816(acc[mt][nt], ah, bp[o], bp[o + 1]);
                    mma16816(acc[mt][nt], ah, lp[o], lp[o + 1]);
                    mma16816(acc[mt][nt], al, bp[o], bp[o + 1]);
                }
            }
        }
    }

    if (MODE >= 1) {
        s_dn[tid] = den;
        __syncthreads();
        if (blockIdx.y == 0 && tid < 128) {
            float ds = s_dn[tid] + s_dn[tid + 128];
            if (MODE == 1) g_den1[z][i0 + tid] = ds; else g_den2[i0 + tid] = ds;
        }
    }

#pragma unroll
    for (int mt = 0; mt < 4; ++mt) {
        int row = i0 + warp_m * 64 + mt * 16 + (lane >> 2);
#pragma unroll
        for (int nt = 0; nt < 4; ++nt) {
            int col = n0 + warp_n * 32 + nt * 8 + (lane & 3) * 2;
            float c0 = acc[mt][nt][0], c1 = acc[mt][nt][1];
            float c2 = acc[mt][nt][2], c3 = acc[mt][nt][3];
            if (MODE == 0) {
                *(float2*)&g_H[z][(size_t)row * D1 + col] = make_float2(c0, c1);
                *(float2*)&g_H[z][(size_t)(row + 8) * D1 + col] = make_float2(c2, c3);
            } else if (MODE == 1) {
                *(float2*)&g_num1[z][(size_t)row * D1 + col] = make_float2(c0, c1);
                *(float2*)&g_num1[z][(size_t)(row + 8) * D1 + col] = make_float2(c2, c3);
            } else {
                *(float2*)&g_num2[(size_t)row * D2 + col] = make_float2(c0, c1);
                *(float2*)&g_num2[(size_t)(row + 8) * D2 + col] = make_float2(c2, c3);
            }
        }
    }
}

template <int ACT>
__global__ __launch_bounds__(256) void k_gemm(
    const float* __restrict__ A, const float* __restrict__ W,
    const float* __restrict__ bias, float* __restrict__ C, int M, int K, int N)
{
    __shared__ float a_s[32][65];
    __shared__ float w_s[32][64];
    int m0 = blockIdx.x * 64, n0 = blockIdx.y * 64;
    int tid = threadIdx.x, ty = tid >> 4, tx = tid & 15;
    float acc[4][4];
#pragma unroll
    for (int r = 0; r < 4; r++)
#pragma unroll
        for (int c = 0; c < 4; c++) acc[r][c] = 0.f;
    for (int k0 = 0; k0 < K; k0 += 32) {
        {
            int m = tid & 63, kq = (tid >> 6) * 8;
            const float* ap = A + (size_t)(m0 + m) * K + k0 + kq;
            float4 v0 = *(const float4*)ap, v1 = *(const float4*)(ap + 4);
            a_s[kq + 0][m] = v0.x; a_s[kq + 1][m] = v0.y;
            a_s[kq + 2][m] = v0.z; a_s[kq + 3][m] = v0.w;
            a_s[kq + 4][m] = v1.x; a_s[kq + 5][m] = v1.y;
            a_s[kq + 6][m] = v1.z; a_s[kq + 7][m] = v1.w;
        }
        {
            int k = tid >> 3, nq = (tid & 7) * 8;
            const float* wp = W + (size_t)(k0 + k) * N + n0 + nq;
            *(float4*)&w_s[k][nq] = *(const float4*)wp;
            *(float4*)&w_s[k][nq + 4] = *(const float4*)(wp + 4);
        }
        __syncthreads();
#pragma unroll 8
        for (int k = 0; k < 32; k++) {
            float av[4];
#pragma unroll
            for (int r = 0; r < 4; r++) av[r] = a_s[k][ty * 4 + r];
            float4 wv = *(float4*)&w_s[k][tx * 4];
            float bv[4] = {wv.x, wv.y, wv.z, wv.w};
#pragma unroll
            for (int r = 0; r < 4; r++)
#pragma unroll
                for (int c = 0; c < 4; c++) acc[r][c] += av[r] * bv[c];
        }
        __syncthreads();
    }
    float bb[4] = {0.f, 0.f, 0.f, 0.f};
    if (bias) {
#pragma unroll
        for (int c = 0; c < 4; c++) bb[c] = bias[n0 + tx * 4 + c];
    }
#pragma unroll
    for (int r = 0; r < 4; r++) {
        float4 o;
        float v0 = acc[r][0] + bb[0], v1 = acc[r][1] + bb[1];
        float v2 = acc[r][2] + bb[2], v3 = acc[r][3] + bb[3];
        if (ACT == 1) { v0 = eluf(v0); v1 = eluf(v1); v2 = eluf(v2); v3 = eluf(v3); }
        o.x = v0; o.y = v1; o.z = v2; o.w = v3;
        *(float4*)&C[(size_t)(m0 + ty * 4 + r) * N + n0 + tx * 4] = o;
    }
}

__global__ void k_st(const float* __restrict__ head_a) {
    int h = blockIdx.y;
    int warp = threadIdx.x >> 5, lane = threadIdx.x & 31;
    int i = blockIdx.x * 8 + warp;
    const float* H = g_H[h] + (size_t)i * D1;
    const float* ah = head_a + h * 2 * D1;
    float s = 0.f, t = 0.f;
#pragma unroll
    for (int d = lane; d < D1; d += 32) {
        float hv = H[d];
        s += hv * ah[d];
        t += hv * ah[D1 + d];
    }
#pragma unroll
    for (int o = 16; o; o >>= 1) {
        s += __shfl_xor_sync(0xffffffffu, s, o);
        t += __shfl_xor_sync(0xffffffffu, t, o);
    }
    if (!lane) { g_s1[h][i] = s; g_t1[h][i] = t; }
}

__global__ void k_fac1() {
    int h = blockIdx.x;
    __shared__ float red[1024];
    float m = -1e30f;
    for (int i = threadIdx.x; i < N_NODES; i += 1024) m = fmaxf(m, g_t1[h][i]);
    red[threadIdx.x] = m;
    __syncthreads();
    for (int s = 512; s; s >>= 1) {
        if (threadIdx.x < s) red[threadIdx.x] = fmaxf(red[threadIdx.x], red[threadIdx.x + s]);
        __syncthreads();
    }
    float tmax = red[0];
    for (int i = threadIdx.x; i < N_NODES; i += 1024) {
        float s_ = g_s1[h][i], t_ = g_t1[h][i];
        float v = s_ + tmax;
        float mm = v > 0.f ? v : ALPHAF * v;
        g_p1[h][i]  = expf(v - mm);
        g_q1[h][i]  = expf(ALPHAF * v - mm);
        g_b1[h][i]  = expf(t_ - tmax);
        g_d1[h][i]  = expf(ALPHAF * (t_ - tmax));
        g_th1[h][i] = -s_;
    }
}

__global__ void k_epi1(const float* __restrict__ head_b) {
    int i = blockIdx.x, c = threadIdx.x;
    __shared__ float red[256];
    float o[2];
#pragma unroll
    for (int h = 0; h < 2; h++) {
        float v = g_num1[h][(size_t)i * D1 + c] / g_den1[h][i];
        float e = eluf(v);
        red[c] = e * e;
        __syncthreads();
        for (int s = 128; s; s >>= 1) {
            if (c < s) red[c] += red[c + s];
            __syncthreads();
        }
        float nrm = sqrtf(red[0]);
        __syncthreads();
        o[h] = e / fmaxf(nrm, 1e-12f) + head_b[h * D1 + c];
    }
    g_z[(size_t)i * D1 + c] = eluf(0.5f * (o[0] + o[1]));
}

__global__ void k_conv(const float* __restrict__ conv_w, const float* __restrict__ conv_cb,
                       const float* __restrict__ conv_a) {
    int i = blockIdx.x, j = threadIdx.x;
    __shared__ float zr[D1];
    __shared__ float wk[132];
    __shared__ float red[128];
    zr[j]       = g_z[(size_t)i * D1 + j];
    zr[j + 128] = g_z[(size_t)i * D1 + j + 128];
    wk[j] = conv_w[j];
    if (j == 0) wk[128] = conv_w[128];
    __syncthreads();
    float acc = conv_cb[0];
#pragma unroll 4
    for (int k = 0; k < 129; k++) acc += zr[j + k] * wk[k];
    g_hc[(size_t)i * D2 + j] = acc;
    red[j] = acc * conv_a[j];
    __syncthreads();
    for (int s = 64; s; s >>= 1) {
        if (j < s) red[j] += red[j + s];
        __syncthreads();
    }
    if (j == 0) g_s2[i] = red[0];
    __syncthreads();
    red[j] = acc * conv_a[128 + j];
    __syncthreads();
    for (int s = 64; s; s >>= 1) {
        if (j < s) red[j] += red[j + s];
        __syncthreads();
    }
    if (j == 0) g_t2[i] = red[0];
}

__global__ void k_fac2() {
    __shared__ float red[1024];
    float m = -1e30f;
    for (int i = threadIdx.x; i < N_NODES; i += 1024) m = fmaxf(m, g_t2[i]);
    red[threadIdx.x] = m;
    __syncthreads();
    for (int s = 512; s; s >>= 1) {
        if (threadIdx.x < s) red[threadIdx.x] = fmaxf(red[threadIdx.x], red[threadIdx.x + s]);
        __syncthreads();
    }
    float tmax = red[0];
    for (int i = threadIdx.x; i < N_NODES; i += 1024) {
        float s_ = g_s2[i], t_ = g_t2[i];
        float v = s_ + tmax;
        float mm = v > 0.f ? v : (expf(v) - 1.f);
        g_P2[i]  = expf(v - mm);
        g_R2[i]  = expf(-1.f - mm);
        g_Es[i]  = expf(fminf(fmaxf(s_, -60.f), 60.f));
        g_B2[i]  = expf(t_ - tmax);
        g_Et[i]  = expf(fminf(fmaxf(t_, -60.f), 60.f));
        g_th2[i] = -s_;
    }
}

__global__ void k_epi2(const float* __restrict__ conv_b) {
    int i = blockIdx.x, c = threadIdx.x;
    __shared__ float red[128];
    float v = g_num2[(size_t)i * D2 + c] / g_den2[i];
    float e = eluf(v);
    red[c] = e * e;
    __syncthreads();
    for (int s = 64; s; s >>= 1) {
        if (c < s) red[c] += red[c + s];
        __syncthreads();
    }
    float nrm = sqrtf(red[0]);
    g_embed[(size_t)i * D2 + c] = e / fmaxf(nrm, 1e-12f) + conv_b[c];
}

__global__ void k_pred(const int* __restrict__ ts, float* __restrict__ out) {
    int p = blockIdx.x * 8 + (threadIdx.x >> 5);
    if (p >= NPAIRS) return;
    int lane = threadIdx.x & 31;
    int i = ts[2 * p], j = ts[2 * p + 1];
    float a = g_tf[i * 64 + lane] * g_tg[j * 64 + lane]
            + g_tf[i * 64 + 32 + lane] * g_tg[j * 64 + 32 + lane];
#pragma unroll
    for (int o = 16; o; o >>= 1) a += __shfl_xor_sync(0xffffffffu, a, o);
    if (!lane) out[p] = a;
}

extern "C" void kernel_launch(void* const* d_in, const int* in_sizes, int n_in,
                              void* d_out, int out_size) {
    const float* x       = (const float*)d_in[0];
    const int*   adj     = (const int*)d_in[1];
    const int*   tsamp   = (const int*)d_in[2];
    const float* head_W  = (const float*)d_in[3];
    const float* head_a  = (const float*)d_in[4];
    const float* head_b  = (const float*)d_in[5];
    const float* conv_w  = (const float*)d_in[6];
    const float* conv_cb = (const float*)d_in[7];
    const float* conv_a  = (const float*)d_in[8];
    const float* conv_b  = (const float*)d_in[9];
    const float* tf_w1   = (const float*)d_in[10];
    const float* tf_b1   = (const float*)d_in[11];
    const float* tf_w2   = (const float*)d_in[12];
    const float* tf_b2   = (const float*)d_in[13];
    const float* tg_w1   = (const float*)d_in[14];
    const float* tg_b1   = (const float*)d_in[15];
    const float* tg_w2   = (const float*)d_in[16];
    const float* tg_b2   = (const float*)d_in[17];
    float* out = (float*)d_out;

    float *pEmbed, *pMid0, *pMid1, *pTf, *pTg;
    cudaGetSymbolAddress((void**)&pEmbed, g_embed);
    cudaGetSymbolAddress((void**)&pMid0, g_mid);
    pMid1 = pMid0 + (size_t)N_NODES * D2;
    cudaGetSymbolAddress((void**)&pTf, g_tf);
    cudaGetSymbolAddress((void**)&pTg, g_tg);

    const int SMEM_MM = 143360;   // 4096 + 4*34816
    cudaFuncSetAttribute(k_mma<0>, cudaFuncAttributeMaxDynamicSharedMemorySize, SMEM_MM);
    cudaFuncSetAttribute(k_mma<1>, cudaFuncAttributeMaxDynamicSharedMemorySize, SMEM_MM);
    cudaFuncSetAttribute(k_mma<2>, cudaFuncAttributeMaxDynamicSharedMemorySize, SMEM_MM);

    k_pack<<<(N_NODES * NW) / 8, 256>>>(adj);

    k_mma<0><<<dim3(N_NODES / 128, D1 / 128, NHEAD), 256, SMEM_MM>>>(x, head_W);
    k_st<<<dim3(N_NODES / 8, NHEAD), 256>>>(head_a);
    k_fac1<<<NHEAD, 1024>>>();
    k_mma<1><<<dim3(N_NODES / 128, D1 / 128, NHEAD), 256, SMEM_MM>>>(x, head_W);
    k_epi1<<<N_NODES, 256>>>(head_b);
    k_conv<<<N_NODES, 128>>>(conv_w, conv_cb, conv_a);
    k_fac2<<<1, 1024>>>();
    k_mma<2><<<dim3(N_NODES / 128, 1, 1), 256, SMEM_MM>>>(x, head_W);
    k_epi2<<<N_NODES, 128>>>(conv_b);

    k_gemm<1><<<dim3(N_NODES / 64, D2 / 64), 256>>>(pEmbed, tf_w1, tf_b1, pMid0, N_NODES, D2, D2);
    k_gemm<1><<<dim3(N_NODES / 64, 1), 256>>>(pMid0, tf_w2, tf_b2, pTf, N_NODES, D2, 64);
    k_gemm<1><<<dim3(N_NODES / 64, D2 / 64), 256>>>(pEmbed, tg_w1, tg_b1, pMid1, N_NODES, D2, D2);
    k_gemm<1><<<dim3(N_NODES / 64, 1), 256>>>(pMid1, tg_w2, tg_b2, pTg, N_NODES, D2, 64);

    k_pred<<<(NPAIRS + 7) / 8, 256>>>(tsamp, out);
}

// round 13
// speedup vs baseline: 2.0638x; 1.0673x over previous
#include <cuda_runtime.h>
#include <cuda_bf16.h>
#include <cstdint>
#include <math.h>

#define N_NODES 8192
#define INDIM   768
#define D1      256
#define D2      128
#define NHEAD   2
#define ALPHAF  0.2f
#define NPAIRS  100000
#define NW      (N_NODES/32)

__device__ unsigned g_adj[N_NODES * NW];
__device__ float g_H[NHEAD][N_NODES * D1];
__device__ __nv_bfloat16 g_Hhi[NHEAD][N_NODES * D1];
__device__ __nv_bfloat16 g_Hlo[NHEAD][N_NODES * D1];
__device__ __nv_bfloat16 g_xhi[N_NODES * INDIM];
__device__ __nv_bfloat16 g_xlo[N_NODES * INDIM];
__device__ __nv_bfloat16 g_Whi[NHEAD * INDIM * D1];
__device__ __nv_bfloat16 g_Wlo[NHEAD * INDIM * D1];
__device__ float g_s1[NHEAD][N_NODES], g_t1[NHEAD][N_NODES];
__device__ float g_p1[NHEAD][N_NODES], g_q1[NHEAD][N_NODES], g_th1[NHEAD][N_NODES];
__device__ float g_b1[NHEAD][N_NODES], g_d1[NHEAD][N_NODES];
__device__ float g_num1[NHEAD][N_NODES * D1];
__device__ float g_den1[NHEAD][N_NODES];
__device__ float g_z[N_NODES * D1];
__device__ float g_hc[N_NODES * D2];
__device__ __nv_bfloat16 g_hchi[N_NODES * D2];
__device__ __nv_bfloat16 g_hclo[N_NODES * D2];
__device__ float g_s2[N_NODES], g_t2[N_NODES];
__device__ float g_P2[N_NODES], g_R2[N_NODES], g_Es[N_NODES], g_th2[N_NODES];
__device__ float g_B2[N_NODES], g_Et[N_NODES];
__device__ float g_num2[N_NODES * D2];
__device__ float g_den2[N_NODES];
__device__ float g_embed[N_NODES * D2];
__device__ float g_mid[2][N_NODES * D2];
__device__ float g_tf[N_NODES * 64];
__device__ float g_tg[N_NODES * 64];

__device__ __forceinline__ float eluf(float x) { return x > 0.f ? x : (expf(x) - 1.f); }
__device__ __forceinline__ uint32_t smem_u32(const void* p) {
    uint32_t a;
    asm("{ .reg .u64 t; cvta.to.shared.u64 t, %1; cvt.u32.u64 %0, t; }" : "=r"(a) : "l"(p));
    return a;
}
__device__ __forceinline__ void ldsm4(unsigned* f, uint32_t addr) {
    asm volatile("ldmatrix.sync.aligned.m8n8.x4.shared.b16 {%0,%1,%2,%3}, [%4];"
                 : "=r"(f[0]), "=r"(f[1]), "=r"(f[2]), "=r"(f[3]) : "r"(addr));
}
__device__ __forceinline__ void ldsm4t(unsigned* f, uint32_t addr) {
    asm volatile("ldmatrix.sync.aligned.m8n8.x4.trans.shared.b16 {%0,%1,%2,%3}, [%4];"
                 : "=r"(f[0]), "=r"(f[1]), "=r"(f[2]), "=r"(f[3]) : "r"(addr));
}
__device__ __forceinline__ void mma16816(float* c, const unsigned* a, unsigned b0, unsigned b1) {
    asm volatile("mma.sync.aligned.m16n8k16.row.col.f32.bf16.bf16.f32 "
                 "{%0,%1,%2,%3}, {%4,%5,%6,%7}, {%8,%9}, {%0,%1,%2,%3};"
                 : "+f"(c[0]), "+f"(c[1]), "+f"(c[2]), "+f"(c[3])
                 : "r"(a[0]), "r"(a[1]), "r"(a[2]), "r"(a[3]), "r"(b0), "r"(b1));
}
__device__ __forceinline__ void sp2(float a, float b, unsigned& h, unsigned& l) {
    __nv_bfloat162 hb = __floats2bfloat162_rn(a, b);
    __nv_bfloat162 lb = __floats2bfloat162_rn(a - __bfloat162float(hb.x),
                                              b - __bfloat162float(hb.y));
    h = *reinterpret_cast<unsigned*>(&hb);
    l = *reinterpret_cast<unsigned*>(&lb);
}

__global__ void k_pack(const int* __restrict__ adj) {
    int w = blockIdx.x * 8 + (threadIdx.x >> 5);
    int lane = threadIdx.x & 31;
    unsigned m = __ballot_sync(0xffffffffu, adj[w * 32 + lane] > 0);
    if (lane == 0) g_adj[w] = m;
}

// fp32 -> (hi, lo) bf16 arrays, 8 elems/thread
__global__ void k_split(const float* __restrict__ s,
                        __nv_bfloat16* __restrict__ hi,
                        __nv_bfloat16* __restrict__ lo, int n) {
    int i = (blockIdx.x * blockDim.x + threadIdx.x) * 8;
    if (i < n) {
        float4 v0 = *(const float4*)(s + i);
        float4 v1 = *(const float4*)(s + i + 4);
        uint4 h, l;
        sp2(v0.x, v0.y, h.x, l.x); sp2(v0.z, v0.w, h.y, l.y);
        sp2(v1.x, v1.y, h.z, l.z); sp2(v1.z, v1.w, h.w, l.w);
        *(uint4*)(hi + i) = h;
        *(uint4*)(lo + i) = l;
    }
}

// MODE 0: g_H = x @ head_W ; MODE 1: GAT1 num/den ; MODE 2: GAT2 num/den
// Full-N blocks: grid (M/128, 1, z). 8 warps = 2m x 4n, warp tile 64 x DTOT/4.
// Split-precision bf16 (hi+lo, 3-term products), B operands pre-split in GMEM.
template <int MODE>
__global__ __launch_bounds__(256, 1) void k_mma(const float* __restrict__ dummy) {
    constexpr int NCH  = (MODE == 0) ? (INDIM / 128) : (N_NODES / 128);
    constexpr int DTOT = (MODE == 2) ? D2 : D1;
    constexpr int AST = 136, BST = DTOT + 8;
    constexpr int NT = DTOT / 32;         // n-tiles (8-wide) per warp: 8 or 4
    constexpr int NP = NT / 2;            // ldsm4t pairs per warp: 4 or 2
    constexpr int BITER = (128 * DTOT / 8) / 256;

    extern __shared__ char smem[];
    float* s_f0 = (float*)smem;
    float* s_f1 = (float*)(smem + 512);
    float* s_t  = (float*)(smem + 1024);
    float* s_dn = (float*)(smem + 1536);
    __nv_bfloat16* a_hi = (__nv_bfloat16*)(smem + 4096);
    __nv_bfloat16* a_lo = (__nv_bfloat16*)(smem + 38912);
    __nv_bfloat16* b_hi = (__nv_bfloat16*)(smem + 73728);
    __nv_bfloat16* b_lo = (__nv_bfloat16*)(smem + 73728 + 128 * BST * 2);
    uint32_t uah = smem_u32(a_hi), ual = smem_u32(a_lo);
    uint32_t ubh = smem_u32(b_hi), ubl = smem_u32(b_lo);

    int tid = threadIdx.x, wid = tid >> 5, lane = tid & 31;
    int i0 = blockIdx.x * 128, z = blockIdx.z;
    int warp_m = wid >> 2, warp_n = wid & 3;
    int r = tid & 127, half = tid >> 7;

    float rf0 = 0.f, rf1 = 0.f, rf2 = 0.f, rth = 0.f, den = 0.f;
    const unsigned* adjrow = nullptr;
    if (MODE == 1) {
        rf0 = g_p1[z][i0 + r]; rf1 = g_q1[z][i0 + r]; rth = g_th1[z][i0 + r];
        adjrow = g_adj + (size_t)(i0 + r) * NW;
    } else if (MODE == 2) {
        rf0 = g_P2[i0 + r]; rf1 = g_R2[i0 + r]; rf2 = g_Es[i0 + r]; rth = g_th2[i0 + r];
        adjrow = g_adj + (size_t)(i0 + r) * NW;
    }
    const __nv_bfloat16* Bhi = (MODE == 0) ? g_Whi + (size_t)z * INDIM * D1
                               : (MODE == 1 ? g_Hhi[z] : g_hchi);
    const __nv_bfloat16* Blo = (MODE == 0) ? g_Wlo + (size_t)z * INDIM * D1
                               : (MODE == 1 ? g_Hlo[z] : g_hclo);

    float acc[4][NT][4];
#pragma unroll
    for (int a = 0; a < 4; a++)
#pragma unroll
        for (int b = 0; b < NT; b++)
#pragma unroll
            for (int c = 0; c < 4; c++) acc[a][b][c] = 0.f;

    for (int jc = 0; jc < NCH; ++jc) {
        int j0 = jc * 128;
        __syncthreads();
        if (MODE >= 1 && tid < 128) {
            s_f0[tid] = (MODE == 1) ? g_b1[z][j0 + tid] : g_B2[j0 + tid];
            s_f1[tid] = (MODE == 1) ? g_d1[z][j0 + tid] : g_Et[j0 + tid];
            s_t[tid]  = (MODE == 1) ? g_t1[z][j0 + tid] : g_t2[j0 + tid];
        }
        if (MODE >= 1) __syncthreads();
        // B tile: pre-split bf16 copies
#pragma unroll
        for (int it = 0; it < BITER; ++it) {
            int idx = it * 256 + tid;
            int row = idx / (DTOT / 8), q = idx % (DTOT / 8);
            size_t goff = (size_t)(j0 + row) * DTOT + q * 8;
            *(uint4*)(b_hi + row * BST + q * 8) = *(const uint4*)(Bhi + goff);
            *(uint4*)(b_lo + row * BST + q * 8) = *(const uint4*)(Blo + goff);
        }
        // A tile
        if (MODE == 0) {
            size_t aoff = (size_t)(i0 + r) * INDIM + j0 + half * 64;
#pragma unroll
            for (int seg = 0; seg < 8; ++seg) {
                *(uint4*)(a_hi + r * AST + half * 64 + seg * 8) = *(const uint4*)(g_xhi + aoff + seg * 8);
                *(uint4*)(a_lo + r * AST + half * 64 + seg * 8) = *(const uint4*)(g_xlo + aoff + seg * 8);
            }
        } else {
            unsigned w0 = adjrow[jc * 4 + half * 2];
            unsigned w1 = adjrow[jc * 4 + half * 2 + 1];
            const float* f0p = s_f0 + half * 64;
            const float* f1p = s_f1 + half * 64;
            const float* tp  = s_t  + half * 64;
#pragma unroll
            for (int seg = 0; seg < 8; ++seg) {
                unsigned word = (seg < 4) ? w0 : w1;
                float f[8];
#pragma unroll
                for (int e = 0; e < 8; ++e) {
                    int jj = seg * 8 + e;
                    float w = 0.f;
                    if ((word >> (jj & 31)) & 1u) {
                        float b = f0p[jj], d = f1p[jj], t = tp[jj];
                        if (MODE == 1) {
                            w = (t > rth) ? rf0 * b : rf1 * d;
                        } else {
                            if (t > rth) w = rf0 * b;
                            else {
                                float g = rf2 * d;
                                float eg = 1.f + g * (1.f + g * (0.5f + g * (0.16666667f +
                                           g * (0.041666668f + g * (0.008333334f + g * (0.0013888889f +
                                           g * (1.9841270e-4f + g * 2.4801587e-5f)))))));
                                w = rf1 * eg;
                            }
                        }
                    }
                    den += w;
                    f[e] = w;
                }
                uint4 h, l;
                sp2(f[0], f[1], h.x, l.x); sp2(f[2], f[3], h.y, l.y);
                sp2(f[4], f[5], h.z, l.z); sp2(f[6], f[7], h.w, l.w);
                *(uint4*)(a_hi + r * AST + half * 64 + seg * 8) = h;
                *(uint4*)(a_lo + r * AST + half * 64 + seg * 8) = l;
            }
        }
        __syncthreads();
        // 3-term split MMA over the 128xDTOTx128 chunk
#pragma unroll
        for (int ks = 0; ks < 8; ++ks) {
            unsigned bh[NP][4], bl[NP][4];
#pragma unroll
            for (int np = 0; np < NP; ++np) {
                uint32_t off = (uint32_t)(((ks * 16 + (lane & 15)) * BST
                               + warp_n * (DTOT / 4) + np * 16 + (lane >> 4) * 8) * 2);
                ldsm4t(bh[np], ubh + off);
                ldsm4t(bl[np], ubl + off);
            }
#pragma unroll
            for (int mt = 0; mt < 4; ++mt) {
                uint32_t aoff = (uint32_t)(((warp_m * 64 + mt * 16 + (lane & 15)) * AST
                                + ks * 16 + (lane >> 4) * 8) * 2);
                unsigned ah[4], al[4];
                ldsm4(ah, uah + aoff);
                ldsm4(al, ual + aoff);
#pragma unroll
                for (int nt = 0; nt < NT; ++nt) {
                    const unsigned* bp = bh[nt >> 1];
                    const unsigned* lp = bl[nt >> 1];
                    int o = (nt & 1) * 2;
                    mma16816(acc[mt][nt], ah, bp[o], bp[o + 1]);
                    mma16816(acc[mt][nt], ah, lp[o], lp[o + 1]);
                    mma16816(acc[mt][nt], al, bp[o], bp[o + 1]);
                }
            }
        }
    }

    if (MODE >= 1) {
        s_dn[tid] = den;
        __syncthreads();
        if (tid < 128) {
            float ds = s_dn[tid] + s_dn[tid + 128];
            if (MODE == 1) g_den1[z][i0 + tid] = ds; else g_den2[i0 + tid] = ds;
        }
    }

#pragma unroll
    for (int mt = 0; mt < 4; ++mt) {
        int row = i0 + warp_m * 64 + mt * 16 + (lane >> 2);
#pragma unroll
        for (int nt = 0; nt < NT; ++nt) {
            int col = warp_n * (DTOT / 4) + nt * 8 + (lane & 3) * 2;
            float c0 = acc[mt][nt][0], c1 = acc[mt][nt][1];
            float c2 = acc[mt][nt][2], c3 = acc[mt][nt][3];
            if (MODE == 0) {
                *(float2*)&g_H[z][(size_t)row * D1 + col] = make_float2(c0, c1);
                *(float2*)&g_H[z][(size_t)(row + 8) * D1 + col] = make_float2(c2, c3);
                unsigned h, l;
                sp2(c0, c1, h, l);
                *(unsigned*)&g_Hhi[z][(size_t)row * D1 + col] = h;
                *(unsigned*)&g_Hlo[z][(size_t)row * D1 + col] = l;
                sp2(c2, c3, h, l);
                *(unsigned*)&g_Hhi[z][(size_t)(row + 8) * D1 + col] = h;
                *(unsigned*)&g_Hlo[z][(size_t)(row + 8) * D1 + col] = l;
            } else if (MODE == 1) {
                *(float2*)&g_num1[z][(size_t)row * D1 + col] = make_float2(c0, c1);
                *(float2*)&g_num1[z][(size_t)(row + 8) * D1 + col] = make_float2(c2, c3);
            } else {
                *(float2*)&g_num2[(size_t)row * D2 + col] = make_float2(c0, c1);
                *(float2*)&g_num2[(size_t)(row + 8) * D2 + col] = make_float2(c2, c3);
            }
        }
    }
}

template <int ACT>
__global__ __launch_bounds__(256) void k_gemm(
    const float* __restrict__ A, const float* __restrict__ W,
    const float* __restrict__ bias, float* __restrict__ C, int M, int K, int N)
{
    __shared__ float a_s[32][65];
    __shared__ float w_s[32][64];
    int m0 = blockIdx.x * 64, n0 = blockIdx.y * 64;
    int tid = threadIdx.x, ty = tid >> 4, tx = tid & 15;
    float acc[4][4];
#pragma unroll
    for (int r = 0; r < 4; r++)
#pragma unroll
        for (int c = 0; c < 4; c++) acc[r][c] = 0.f;
    for (int k0 = 0; k0 < K; k0 += 32) {
        {
            int m = tid & 63, kq = (tid >> 6) * 8;
            const float* ap = A + (size_t)(m0 + m) * K + k0 + kq;
            float4 v0 = *(const float4*)ap, v1 = *(const float4*)(ap + 4);
            a_s[kq + 0][m] = v0.x; a_s[kq + 1][m] = v0.y;
            a_s[kq + 2][m] = v0.z; a_s[kq + 3][m] = v0.w;
            a_s[kq + 4][m] = v1.x; a_s[kq + 5][m] = v1.y;
            a_s[kq + 6][m] = v1.z; a_s[kq + 7][m] = v1.w;
        }
        {
            int k = tid >> 3, nq = (tid & 7) * 8;
            const float* wp = W + (size_t)(k0 + k) * N + n0 + nq;
            *(float4*)&w_s[k][nq] = *(const float4*)wp;
            *(float4*)&w_s[k][nq + 4] = *(const float4*)(wp + 4);
        }
        __syncthreads();
#pragma unroll 8
        for (int k = 0; k < 32; k++) {
            float av[4];
#pragma unroll
            for (int r = 0; r < 4; r++) av[r] = a_s[k][ty * 4 + r];
            float4 wv = *(float4*)&w_s[k][tx * 4];
            float bv[4] = {wv.x, wv.y, wv.z, wv.w};
#pragma unroll
            for (int r = 0; r < 4; r++)
#pragma unroll
                for (int c = 0; c < 4; c++) acc[r][c] += av[r] * bv[c];
        }
        __syncthreads();
    }
    float bb[4] = {0.f, 0.f, 0.f, 0.f};
    if (bias) {
#pragma unroll
        for (int c = 0; c < 4; c++) bb[c] = bias[n0 + tx * 4 + c];
    }
#pragma unroll
    for (int r = 0; r < 4; r++) {
        float4 o;
        float v0 = acc[r][0] + bb[0], v1 = acc[r][1] + bb[1];
        float v2 = acc[r][2] + bb[2], v3 = acc[r][3] + bb[3];
        if (ACT == 1) { v0 = eluf(v0); v1 = eluf(v1); v2 = eluf(v2); v3 = eluf(v3); }
        o.x = v0; o.y = v1; o.z = v2; o.w = v3;
        *(float4*)&C[(size_t)(m0 + ty * 4 + r) * N + n0 + tx * 4] = o;
    }
}

__global__ void k_st(const float* __restrict__ head_a) {
    int h = blockIdx.y;
    int warp = threadIdx.x >> 5, lane = threadIdx.x & 31;
    int i = blockIdx.x * 8 + warp;
    const float* H = g_H[h] + (size_t)i * D1;
    const float* ah = head_a + h * 2 * D1;
    float s = 0.f, t = 0.f;
#pragma unroll
    for (int d = lane; d < D1; d += 32) {
        float hv = H[d];
        s += hv * ah[d];
        t += hv * ah[D1 + d];
    }
#pragma unroll
    for (int o = 16; o; o >>= 1) {
        s += __shfl_xor_sync(0xffffffffu, s, o);
        t += __shfl_xor_sync(0xffffffffu, t, o);
    }
    if (!lane) { g_s1[h][i] = s; g_t1[h][i] = t; }
}

__global__ void k_fac1() {
    int h = blockIdx.x;
    __shared__ float red[1024];
    float m = -1e30f;
    for (int i = threadIdx.x; i < N_NODES; i += 1024) m = fmaxf(m, g_t1[h][i]);
    red[threadIdx.x] = m;
    __syncthreads();
    for (int s = 512; s; s >>= 1) {
        if (threadIdx.x < s) red[threadIdx.x] = fmaxf(red[threadIdx.x], red[threadIdx.x + s]);
        __syncthreads();
    }
    float tmax = red[0];
    for (int i = threadIdx.x; i < N_NODES; i += 1024) {
        float s_ = g_s1[h][i], t_ = g_t1[h][i];
        float v = s_ + tmax;
        float mm = v > 0.f ? v : ALPHAF * v;
        g_p1[h][i]  = expf(v - mm);
        g_q1[h][i]  = expf(ALPHAF * v - mm);
        g_b1[h][i]  = expf(t_ - tmax);
        g_d1[h][i]  = expf(ALPHAF * (t_ - tmax));
        g_th1[h][i] = -s_;
    }
}

__global__ void k_epi1(const float* __restrict__ head_b) {
    int i = blockIdx.x, c = threadIdx.x;
    __shared__ float red[256];
    float o[2];
#pragma unroll
    for (int h = 0; h < 2; h++) {
        float v = g_num1[h][(size_t)i * D1 + c] / g_den1[h][i];
        float e = eluf(v);
        red[c] = e * e;
        __syncthreads();
        for (int s = 128; s; s >>= 1) {
            if (c < s) red[c] += red[c + s];
            __syncthreads();
        }
        float nrm = sqrtf(red[0]);
        __syncthreads();
        o[h] = e / fmaxf(nrm, 1e-12f) + head_b[h * D1 + c];
    }
    g_z[(size_t)i * D1 + c] = eluf(0.5f * (o[0] + o[1]));
}

__global__ void k_conv(const float* __restrict__ conv_w, const float* __restrict__ conv_cb,
                       const float* __restrict__ conv_a) {
    int i = blockIdx.x, j = threadIdx.x;
    __shared__ float zr[D1];
    __shared__ float wk[132];
    __shared__ float red[128];
    zr[j]       = g_z[(size_t)i * D1 + j];
    zr[j + 128] = g_z[(size_t)i * D1 + j + 128];
    wk[j] = conv_w[j];
    if (j == 0) wk[128] = conv_w[128];
    __syncthreads();
    float acc = conv_cb[0];
#pragma unroll 4
    for (int k = 0; k < 129; k++) acc += zr[j + k] * wk[k];
    g_hc[(size_t)i * D2 + j] = acc;
    __nv_bfloat16 hb = __float2bfloat16(acc);
    g_hchi[(size_t)i * D2 + j] = hb;
    g_hclo[(size_t)i * D2 + j] = __float2bfloat16(acc - __bfloat162float(hb));
    red[j] = acc * conv_a[j];
    __syncthreads();
    for (int s = 64; s; s >>= 1) {
        if (j < s) red[j] += red[j + s];
        __syncthreads();
    }
    if (j == 0) g_s2[i] = red[0];
    __syncthreads();
    red[j] = acc * conv_a[128 + j];
    __syncthreads();
    for (int s = 64; s; s >>= 1) {
        if (j < s) red[j] += red[j + s];
        __syncthreads();
    }
    if (j == 0) g_t2[i] = red[0];
}

__global__ void k_fac2() {
    __shared__ float red[1024];
    float m = -1e30f;
    for (int i = threadIdx.x; i < N_NODES; i += 1024) m = fmaxf(m, g_t2[i]);
    red[threadIdx.x] = m;
    __syncthreads();
    for (int s = 512; s; s >>= 1) {
        if (threadIdx.x < s) red[threadIdx.x] = fmaxf(red[threadIdx.x], red[threadIdx.x + s]);
        __syncthreads();
    }
    float tmax = red[0];
    for (int i = threadIdx.x; i < N_NODES; i += 1024) {
        float s_ = g_s2[i], t_ = g_t2[i];
        float v = s_ + tmax;
        float mm = v > 0.f ? v : (expf(v) - 1.f);
        g_P2[i]  = expf(v - mm);
        g_R2[i]  = expf(-1.f - mm);
        g_Es[i]  = expf(fminf(fmaxf(s_, -60.f), 60.f));
        g_B2[i]  = expf(t_ - tmax);
        g_Et[i]  = expf(fminf(fmaxf(t_, -60.f), 60.f));
        g_th2[i] = -s_;
    }
}

__global__ void k_epi2(const float* __restrict__ conv_b) {
    int i = blockIdx.x, c = threadIdx.x;
    __shared__ float red[128];
    float v = g_num2[(size_t)i * D2 + c] / g_den2[i];
    float e = eluf(v);
    red[c] = e * e;
    __syncthreads();
    for (int s = 64; s; s >>= 1) {
        if (c < s) red[c] += red[c + s];
        __syncthreads();
    }
    float nrm = sqrtf(red[0]);
    g_embed[(size_t)i * D2 + c] = e / fmaxf(nrm, 1e-12f) + conv_b[c];
}

__global__ void k_pred(const int* __restrict__ ts, float* __restrict__ out) {
    int p = blockIdx.x * 8 + (threadIdx.x >> 5);
    if (p >= NPAIRS) return;
    int lane = threadIdx.x & 31;
    int i = ts[2 * p], j = ts[2 * p + 1];
    float a = g_tf[i * 64 + lane] * g_tg[j * 64 + lane]
            + g_tf[i * 64 + 32 + lane] * g_tg[j * 64 + 32 + lane];
#pragma unroll
    for (int o = 16; o; o >>= 1) a += __shfl_xor_sync(0xffffffffu, a, o);
    if (!lane) out[p] = a;
}

extern "C" void kernel_launch(void* const* d_in, const int* in_sizes, int n_in,
                              void* d_out, int out_size) {
    const float* x       = (const float*)d_in[0];
    const int*   adj     = (const int*)d_in[1];
    const int*   tsamp   = (const int*)d_in[2];
    const float* head_W  = (const float*)d_in[3];
    const float* head_a  = (const float*)d_in[4];
    const float* head_b  = (const float*)d_in[5];
    const float* conv_w  = (const float*)d_in[6];
    const float* conv_cb = (const float*)d_in[7];
    const float* conv_a  = (const float*)d_in[8];
    const float* conv_b  = (const float*)d_in[9];
    const float* tf_w1   = (const float*)d_in[10];
    const float* tf_b1   = (const float*)d_in[11];
    const float* tf_w2   = (const float*)d_in[12];
    const float* tf_b2   = (const float*)d_in[13];
    const float* tg_w1   = (const float*)d_in[14];
    const float* tg_b1   = (const float*)d_in[15];
    const float* tg_w2   = (const float*)d_in[16];
    const float* tg_b2   = (const float*)d_in[17];
    float* out = (float*)d_out;

    float *pEmbed, *pMid0, *pMid1, *pTf, *pTg;
    __nv_bfloat16 *pXhi, *pXlo, *pWhi, *pWlo;
    cudaGetSymbolAddress((void**)&pEmbed, g_embed);
    cudaGetSymbolAddress((void**)&pMid0, g_mid);
    pMid1 = pMid0 + (size_t)N_NODES * D2;
    cudaGetSymbolAddress((void**)&pTf, g_tf);
    cudaGetSymbolAddress((void**)&pTg, g_tg);
    cudaGetSymbolAddress((void**)&pXhi, g_xhi);
    cudaGetSymbolAddress((void**)&pXlo, g_xlo);
    cudaGetSymbolAddress((void**)&pWhi, g_Whi);
    cudaGetSymbolAddress((void**)&pWlo, g_Wlo);

    // smem: 4096 + A(2*34816) + B(2*128*(DTOT+8)*2)
    const int SMEM_BIG = 73728 + 2 * 128 * (D1 + 8) * 2;   // 208896 (DTOT=256)
    const int SMEM_SML = 73728 + 2 * 128 * (D2 + 8) * 2;   // 143360 (DTOT=128)
    cudaFuncSetAttribute(k_mma<0>, cudaFuncAttributeMaxDynamicSharedMemorySize, SMEM_BIG);
    cudaFuncSetAttribute(k_mma<1>, cudaFuncAttributeMaxDynamicSharedMemorySize, SMEM_BIG);
    cudaFuncSetAttribute(k_mma<2>, cudaFuncAttributeMaxDynamicSharedMemorySize, SMEM_SML);

    k_pack<<<(N_NODES * NW) / 8, 256>>>(adj);
    k_split<<<(N_NODES * INDIM / 8 + 255) / 256, 256>>>(x, pXhi, pXlo, N_NODES * INDIM);
    k_split<<<(NHEAD * INDIM * D1 / 8 + 255) / 256, 256>>>(head_W, pWhi, pWlo, NHEAD * INDIM * D1);

    k_mma<0><<<dim3(N_NODES / 128, 1, NHEAD), 256, SMEM_BIG>>>(x);
    k_st<<<dim3(N_NODES / 8, NHEAD), 256>>>(head_a);
    k_fac1<<<NHEAD, 1024>>>();
    k_mma<1><<<dim3(N_NODES / 128, 1, NHEAD), 256, SMEM_BIG>>>(x);
    k_epi1<<<N_NODES, 256>>>(head_b);
    k_conv<<<N_NODES, 128>>>(conv_w, conv_cb, conv_a);
    k_fac2<<<1, 1024>>>();
    k_mma<2><<<dim3(N_NODES / 128, 1, 1), 256, SMEM_SML>>>(x);
    k_epi2<<<N_NODES, 128>>>(conv_b);

    k_gemm<1><<<dim3(N_NODES / 64, D2 / 64), 256>>>(pEmbed, tf_w1, tf_b1, pMid0, N_NODES, D2, D2);
    k_gemm<1><<<dim3(N_NODES / 64, 1), 256>>>(pMid0, tf_w2, tf_b2, pTf, N_NODES, D2, 64);
    k_gemm<1><<<dim3(N_NODES / 64, D2 / 64), 256>>>(pEmbed, tg_w1, tg_b1, pMid1, N_NODES, D2, D2);
    k_gemm<1><<<dim3(N_NODES / 64, 1), 256>>>(pMid1, tg_w2, tg_b2, pTg, N_NODES, D2, 64);

    k_pred<<<(NPAIRS + 7) / 8, 256>>>(tsamp, out);
}

// round 14
// speedup vs baseline: 2.7357x; 1.3255x over previous
#include <cuda_runtime.h>
#include <cuda_bf16.h>
#include <cstdint>
#include <math.h>

#define N_NODES 8192
#define INDIM   768
#define D1      256
#define D2      128
#define NHEAD   2
#define ALPHAF  0.2f
#define NPAIRS  100000
#define NW      (N_NODES/32)

__device__ unsigned g_adj[N_NODES * NW];
__device__ float g_H[NHEAD][N_NODES * D1];
__device__ __nv_bfloat16 g_Hhi[NHEAD][N_NODES * D1];
__device__ __nv_bfloat16 g_Hlo[NHEAD][N_NODES * D1];
__device__ __nv_bfloat16 g_xhi[N_NODES * INDIM];
__device__ __nv_bfloat16 g_xlo[N_NODES * INDIM];
__device__ __nv_bfloat16 g_Whi[NHEAD * INDIM * D1];
__device__ __nv_bfloat16 g_Wlo[NHEAD * INDIM * D1];
__device__ float g_s1[NHEAD][N_NODES], g_t1[NHEAD][N_NODES];
__device__ float g_p1[NHEAD][N_NODES], g_q1[NHEAD][N_NODES], g_th1[NHEAD][N_NODES];
__device__ float g_b1[NHEAD][N_NODES], g_d1[NHEAD][N_NODES];
__device__ float g_num1[NHEAD][N_NODES * D1];
__device__ float g_den1[NHEAD][N_NODES];
__device__ float g_z[N_NODES * D1];
__device__ float g_hc[N_NODES * D2];
__device__ __nv_bfloat16 g_hchi[N_NODES * D2];
__device__ __nv_bfloat16 g_hclo[N_NODES * D2];
__device__ float g_s2[N_NODES], g_t2[N_NODES];
__device__ float g_P2[N_NODES], g_R2[N_NODES], g_Es[N_NODES], g_th2[N_NODES];
__device__ float g_B2[N_NODES], g_Et[N_NODES];
__device__ float g_num2[N_NODES * D2];
__device__ float g_den2[N_NODES];
__device__ float g_embed[N_NODES * D2];
__device__ float g_mid[2][N_NODES * D2];
__device__ float g_tf[N_NODES * 64];
__device__ float g_tg[N_NODES * 64];

__device__ __forceinline__ float eluf(float x) { return x > 0.f ? x : (expf(x) - 1.f); }
__device__ __forceinline__ uint32_t smem_u32(const void* p) {
    uint32_t a;
    asm("{ .reg .u64 t; cvta.to.shared.u64 t, %1; cvt.u32.u64 %0, t; }" : "=r"(a) : "l"(p));
    return a;
}
__device__ __forceinline__ void ldsm4(unsigned* f, uint32_t addr) {
    asm volatile("ldmatrix.sync.aligned.m8n8.x4.shared.b16 {%0,%1,%2,%3}, [%4];"
                 : "=r"(f[0]), "=r"(f[1]), "=r"(f[2]), "=r"(f[3]) : "r"(addr));
}
__device__ __forceinline__ void ldsm4t(unsigned* f, uint32_t addr) {
    asm volatile("ldmatrix.sync.aligned.m8n8.x4.trans.shared.b16 {%0,%1,%2,%3}, [%4];"
                 : "=r"(f[0]), "=r"(f[1]), "=r"(f[2]), "=r"(f[3]) : "r"(addr));
}
__device__ __forceinline__ void mma16816(float* c, const unsigned* a, unsigned b0, unsigned b1) {
    asm volatile("mma.sync.aligned.m16n8k16.row.col.f32.bf16.bf16.f32 "
                 "{%0,%1,%2,%3}, {%4,%5,%6,%7}, {%8,%9}, {%0,%1,%2,%3};"
                 : "+f"(c[0]), "+f"(c[1]), "+f"(c[2]), "+f"(c[3])
                 : "r"(a[0]), "r"(a[1]), "r"(a[2]), "r"(a[3]), "r"(b0), "r"(b1));
}
__device__ __forceinline__ void sp2(float a, float b, unsigned& h, unsigned& l) {
    __nv_bfloat162 hb = __floats2bfloat162_rn(a, b);
    __nv_bfloat162 lb = __floats2bfloat162_rn(a - __bfloat162float(hb.x),
                                              b - __bfloat162float(hb.y));
    h = *reinterpret_cast<unsigned*>(&hb);
    l = *reinterpret_cast<unsigned*>(&lb);
}
#define CP_ASYNC16(dst, src) \
    asm volatile("cp.async.cg.shared.global [%0], [%1], 16;" :: "r"(dst), "l"(src))
#define CP_COMMIT() asm volatile("cp.async.commit_group;" ::: "memory")
#define CP_WAIT0()  asm volatile("cp.async.wait_group 0;" ::: "memory")

__global__ void k_pack(const int* __restrict__ adj) {
    int w = blockIdx.x * 8 + (threadIdx.x >> 5);
    int lane = threadIdx.x & 31;
    unsigned m = __ballot_sync(0xffffffffu, adj[w * 32 + lane] > 0);
    if (lane == 0) g_adj[w] = m;
}

__global__ void k_split(const float* __restrict__ s,
                        __nv_bfloat16* __restrict__ hi,
                        __nv_bfloat16* __restrict__ lo, int n) {
    int i = (blockIdx.x * blockDim.x + threadIdx.x) * 8;
    if (i < n) {
        float4 v0 = *(const float4*)(s + i);
        float4 v1 = *(const float4*)(s + i + 4);
        uint4 h, l;
        sp2(v0.x, v0.y, h.x, l.x); sp2(v0.z, v0.w, h.y, l.y);
        sp2(v1.x, v1.y, h.z, l.z); sp2(v1.z, v1.w, h.w, l.w);
        *(uint4*)(hi + i) = h;
        *(uint4*)(lo + i) = l;
    }
}

// MODE 0: g_H = x @ head_W ; MODE 1: GAT1 num/den ; MODE 2: GAT2 num/den
// 512 threads = 16 warps (4m x 4n). MTILE rows/block, full-DTOT columns.
// Split-precision bf16 hi+lo, 3-term MMA; cp.async B prefetch overlapped
// with A-tile build.
template <int MODE>
__global__ __launch_bounds__(512, 1) void k_mma(const float* __restrict__ dummy) {
    constexpr int NCH   = (MODE == 0) ? (INDIM / 128) : (N_NODES / 128);
    constexpr int DTOT  = (MODE == 2) ? D2 : D1;
    constexpr int MTILE = (MODE == 2) ? 64 : 128;
    constexpr int AST = 136, BST = DTOT + 8;
    constexpr int NT = DTOT / 32;            // 8-wide n-tiles per warp
    constexpr int NP = NT / 2;
    constexpr int MT = MTILE / 64;           // 16-row m-tiles per warp (2 or 1)
    constexpr int PARTS = 512 / MTILE;       // threads per row (4 or 8)
    constexpr int JW = 128 / PARTS;          // j per thread (32 or 16)
    constexpr int SEGS = JW / 8;             // 8-wide segs per thread (4 or 2)
    constexpr int BITER = (128 * DTOT / 8) / 512;

    extern __shared__ char smem[];
    float* s_f0 = (float*)smem;
    float* s_f1 = (float*)(smem + 512);
    float* s_t  = (float*)(smem + 1024);
    float* s_dn = (float*)(smem + 1536);     // 512 floats -> ends at 3584
    __nv_bfloat16* a_hi = (__nv_bfloat16*)(smem + 4096);
    __nv_bfloat16* a_lo = (__nv_bfloat16*)(smem + 38912);
    __nv_bfloat16* b_hi = (__nv_bfloat16*)(smem + 73728);
    __nv_bfloat16* b_lo = (__nv_bfloat16*)(smem + 73728 + 128 * BST * 2);
    uint32_t uah = smem_u32(a_hi), ual = smem_u32(a_lo);
    uint32_t ubh = smem_u32(b_hi), ubl = smem_u32(b_lo);

    int tid = threadIdx.x, wid = tid >> 5, lane = tid & 31;
    int i0 = blockIdx.x * MTILE, z = blockIdx.z;
    int warp_m = wid >> 2, warp_n = wid & 3;
    int r = tid & (MTILE - 1);
    int part = tid / MTILE;
    int jbase = part * JW;

    float rf0 = 0.f, rf1 = 0.f, rf2 = 0.f, rth = 0.f, den = 0.f;
    const unsigned* adjrow = nullptr;
    if (MODE == 1) {
        rf0 = g_p1[z][i0 + r]; rf1 = g_q1[z][i0 + r]; rth = g_th1[z][i0 + r];
        adjrow = g_adj + (size_t)(i0 + r) * NW;
    } else if (MODE == 2) {
        rf0 = g_P2[i0 + r]; rf1 = g_R2[i0 + r]; rf2 = g_Es[i0 + r]; rth = g_th2[i0 + r];
        adjrow = g_adj + (size_t)(i0 + r) * NW;
    }
    const __nv_bfloat16* Bhi = (MODE == 0) ? g_Whi + (size_t)z * INDIM * D1
                               : (MODE == 1 ? g_Hhi[z] : g_hchi);
    const __nv_bfloat16* Blo = (MODE == 0) ? g_Wlo + (size_t)z * INDIM * D1
                               : (MODE == 1 ? g_Hlo[z] : g_hclo);

    float acc[MT][NT][4];
#pragma unroll
    for (int a = 0; a < MT; a++)
#pragma unroll
        for (int b = 0; b < NT; b++)
#pragma unroll
            for (int c = 0; c < 4; c++) acc[a][b][c] = 0.f;

    for (int jc = 0; jc < NCH; ++jc) {
        int j0 = jc * 128;
        __syncthreads();   // prev MMA reads done
        // B prefetch (cp.async) — overlaps with factor staging + A build
#pragma unroll
        for (int it = 0; it < BITER; ++it) {
            int idx = it * 512 + tid;
            int row = idx / (DTOT / 8), q = idx % (DTOT / 8);
            size_t goff = (size_t)(j0 + row) * DTOT + q * 8;
            uint32_t doff = (uint32_t)((row * BST + q * 8) * 2);
            CP_ASYNC16(ubh + doff, Bhi + goff);
            CP_ASYNC16(ubl + doff, Blo + goff);
        }
        CP_COMMIT();
        if (MODE >= 1 && tid < 128) {
            s_f0[tid] = (MODE == 1) ? g_b1[z][j0 + tid] : g_B2[j0 + tid];
            s_f1[tid] = (MODE == 1) ? g_d1[z][j0 + tid] : g_Et[j0 + tid];
            s_t[tid]  = (MODE == 1) ? g_t1[z][j0 + tid] : g_t2[j0 + tid];
        }
        if (MODE >= 1) __syncthreads();   // staging visible
        // A tile
        if (MODE == 0) {
            size_t aoff = (size_t)(i0 + r) * INDIM + j0 + jbase;
#pragma unroll
            for (int ss = 0; ss < SEGS; ++ss) {
                *(uint4*)(a_hi + r * AST + jbase + ss * 8) = *(const uint4*)(g_xhi + aoff + ss * 8);
                *(uint4*)(a_lo + r * AST + jbase + ss * 8) = *(const uint4*)(g_xlo + aoff + ss * 8);
            }
        } else {
#pragma unroll
            for (int ss = 0; ss < SEGS; ++ss) {
                int sj = jbase + ss * 8;
                unsigned word = adjrow[jc * 4 + (sj >> 5)];
                float f[8];
#pragma unroll
                for (int e = 0; e < 8; ++e) {
                    int jj = sj + e;
                    float w = 0.f;
                    if ((word >> (jj & 31)) & 1u) {
                        float b = s_f0[jj], d = s_f1[jj], t = s_t[jj];
                        if (MODE == 1) {
                            w = (t > rth) ? rf0 * b : rf1 * d;
                        } else {
                            if (t > rth) w = rf0 * b;
                            else {
                                float g = rf2 * d;
                                float eg = 1.f + g * (1.f + g * (0.5f + g * (0.16666667f +
                                           g * (0.041666668f + g * (0.008333334f + g * (0.0013888889f +
                                           g * (1.9841270e-4f + g * 2.4801587e-5f)))))));
                                w = rf1 * eg;
                            }
                        }
                    }
                    den += w;
                    f[e] = w;
                }
                uint4 h, l;
                sp2(f[0], f[1], h.x, l.x); sp2(f[2], f[3], h.y, l.y);
                sp2(f[4], f[5], h.z, l.z); sp2(f[6], f[7], h.w, l.w);
                *(uint4*)(a_hi + r * AST + sj) = h;
                *(uint4*)(a_lo + r * AST + sj) = l;
            }
        }
        CP_WAIT0();
        __syncthreads();
        // 3-term split MMA over the MTILE x DTOT x 128 chunk
#pragma unroll
        for (int ks = 0; ks < 8; ++ks) {
            unsigned bh[NP][4], bl[NP][4];
#pragma unroll
            for (int np = 0; np < NP; ++np) {
                uint32_t off = (uint32_t)(((ks * 16 + (lane & 15)) * BST
                               + warp_n * (DTOT / 4) + np * 16 + (lane >> 4) * 8) * 2);
                ldsm4t(bh[np], ubh + off);
                ldsm4t(bl[np], ubl + off);
            }
#pragma unroll
            for (int mt = 0; mt < MT; ++mt) {
                uint32_t aoff = (uint32_t)(((warp_m * (MTILE / 4) + mt * 16 + (lane & 15)) * AST
                                + ks * 16 + (lane >> 4) * 8) * 2);
                unsigned ah[4], al[4];
                ldsm4(ah, uah + aoff);
                ldsm4(al, ual + aoff);
#pragma unroll
                for (int nt = 0; nt < NT; ++nt) {
                    const unsigned* bp = bh[nt >> 1];
                    const unsigned* lp = bl[nt >> 1];
                    int o = (nt & 1) * 2;
                    mma16816(acc[mt][nt], ah, bp[o], bp[o + 1]);
                    mma16816(acc[mt][nt], ah, lp[o], lp[o + 1]);
                    mma16816(acc[mt][nt], al, bp[o], bp[o + 1]);
                }
            }
        }
    }

    if (MODE >= 1) {
        s_dn[tid] = den;
        __syncthreads();
        if (tid < MTILE) {
            float ds = 0.f;
#pragma unroll
            for (int p = 0; p < PARTS; ++p) ds += s_dn[p * MTILE + tid];
            if (MODE == 1) g_den1[z][i0 + tid] = ds; else g_den2[i0 + tid] = ds;
        }
    }

#pragma unroll
    for (int mt = 0; mt < MT; ++mt) {
        int row = i0 + warp_m * (MTILE / 4) + mt * 16 + (lane >> 2);
#pragma unroll
        for (int nt = 0; nt < NT; ++nt) {
            int col = warp_n * (DTOT / 4) + nt * 8 + (lane & 3) * 2;
            float c0 = acc[mt][nt][0], c1 = acc[mt][nt][1];
            float c2 = acc[mt][nt][2], c3 = acc[mt][nt][3];
            if (MODE == 0) {
                *(float2*)&g_H[z][(size_t)row * D1 + col] = make_float2(c0, c1);
                *(float2*)&g_H[z][(size_t)(row + 8) * D1 + col] = make_float2(c2, c3);
                unsigned h, l;
                sp2(c0, c1, h, l);
                *(unsigned*)&g_Hhi[z][(size_t)row * D1 + col] = h;
                *(unsigned*)&g_Hlo[z][(size_t)row * D1 + col] = l;
                sp2(c2, c3, h, l);
                *(unsigned*)&g_Hhi[z][(size_t)(row + 8) * D1 + col] = h;
                *(unsigned*)&g_Hlo[z][(size_t)(row + 8) * D1 + col] = l;
            } else if (MODE == 1) {
                *(float2*)&g_num1[z][(size_t)row * D1 + col] = make_float2(c0, c1);
                *(float2*)&g_num1[z][(size_t)(row + 8) * D1 + col] = make_float2(c2, c3);
            } else {
                *(float2*)&g_num2[(size_t)row * D2 + col] = make_float2(c0, c1);
                *(float2*)&g_num2[(size_t)(row + 8) * D2 + col] = make_float2(c2, c3);
            }
        }
    }
}

template <int ACT>
__global__ __launch_bounds__(256) void k_gemm(
    const float* __restrict__ A, const float* __restrict__ W,
    const float* __restrict__ bias, float* __restrict__ C, int M, int K, int N)
{
    __shared__ float a_s[32][65];
    __shared__ float w_s[32][64];
    int m0 = blockIdx.x * 64, n0 = blockIdx.y * 64;
    int tid = threadIdx.x, ty = tid >> 4, tx = tid & 15;
    float acc[4][4];
#pragma unroll
    for (int r = 0; r < 4; r++)
#pragma unroll
        for (int c = 0; c < 4; c++) acc[r][c] = 0.f;
    for (int k0 = 0; k0 < K; k0 += 32) {
        {
            int m = tid & 63, kq = (tid >> 6) * 8;
            const float* ap = A + (size_t)(m0 + m) * K + k0 + kq;
            float4 v0 = *(const float4*)ap, v1 = *(const float4*)(ap + 4);
            a_s[kq + 0][m] = v0.x; a_s[kq + 1][m] = v0.y;
            a_s[kq + 2][m] = v0.z; a_s[kq + 3][m] = v0.w;
            a_s[kq + 4][m] = v1.x; a_s[kq + 5][m] = v1.y;
            a_s[kq + 6][m] = v1.z; a_s[kq + 7][m] = v1.w;
        }
        {
            int k = tid >> 3, nq = (tid & 7) * 8;
            const float* wp = W + (size_t)(k0 + k) * N + n0 + nq;
            *(float4*)&w_s[k][nq] = *(const float4*)wp;
            *(float4*)&w_s[k][nq + 4] = *(const float4*)(wp + 4);
        }
        __syncthreads();
#pragma unroll 8
        for (int k = 0; k < 32; k++) {
            float av[4];
#pragma unroll
            for (int r = 0; r < 4; r++) av[r] = a_s[k][ty * 4 + r];
            float4 wv = *(float4*)&w_s[k][tx * 4];
            float bv[4] = {wv.x, wv.y, wv.z, wv.w};
#pragma unroll
            for (int r = 0; r < 4; r++)
#pragma unroll
                for (int c = 0; c < 4; c++) acc[r][c] += av[r] * bv[c];
        }
        __syncthreads();
    }
    float bb[4] = {0.f, 0.f, 0.f, 0.f};
    if (bias) {
#pragma unroll
        for (int c = 0; c < 4; c++) bb[c] = bias[n0 + tx * 4 + c];
    }
#pragma unroll
    for (int r = 0; r < 4; r++) {
        float4 o;
        float v0 = acc[r][0] + bb[0], v1 = acc[r][1] + bb[1];
        float v2 = acc[r][2] + bb[2], v3 = acc[r][3] + bb[3];
        if (ACT == 1) { v0 = eluf(v0); v1 = eluf(v1); v2 = eluf(v2); v3 = eluf(v3); }
        o.x = v0; o.y = v1; o.z = v2; o.w = v3;
        *(float4*)&C[(size_t)(m0 + ty * 4 + r) * N + n0 + tx * 4] = o;
    }
}

__global__ void k_st(const float* __restrict__ head_a) {
    int h = blockIdx.y;
    int warp = threadIdx.x >> 5, lane = threadIdx.x & 31;
    int i = blockIdx.x * 8 + warp;
    const float* H = g_H[h] + (size_t)i * D1;
    const float* ah = head_a + h * 2 * D1;
    float s = 0.f, t = 0.f;
#pragma unroll
    for (int d = lane; d < D1; d += 32) {
        float hv = H[d];
        s += hv * ah[d];
        t += hv * ah[D1 + d];
    }
#pragma unroll
    for (int o = 16; o; o >>= 1) {
        s += __shfl_xor_sync(0xffffffffu, s, o);
        t += __shfl_xor_sync(0xffffffffu, t, o);
    }
    if (!lane) { g_s1[h][i] = s; g_t1[h][i] = t; }
}

__global__ void k_fac1() {
    int h = blockIdx.x;
    __shared__ float red[1024];
    float m = -1e30f;
    for (int i = threadIdx.x; i < N_NODES; i += 1024) m = fmaxf(m, g_t1[h][i]);
    red[threadIdx.x] = m;
    __syncthreads();
    for (int s = 512; s; s >>= 1) {
        if (threadIdx.x < s) red[threadIdx.x] = fmaxf(red[threadIdx.x], red[threadIdx.x + s]);
        __syncthreads();
    }
    float tmax = red[0];
    for (int i = threadIdx.x; i < N_NODES; i += 1024) {
        float s_ = g_s1[h][i], t_ = g_t1[h][i];
        float v = s_ + tmax;
        float mm = v > 0.f ? v : ALPHAF * v;
        g_p1[h][i]  = expf(v - mm);
        g_q1[h][i]  = expf(ALPHAF * v - mm);
        g_b1[h][i]  = expf(t_ - tmax);
        g_d1[h][i]  = expf(ALPHAF * (t_ - tmax));
        g_th1[h][i] = -s_;
    }
}

__global__ void k_epi1(const float* __restrict__ head_b) {
    int i = blockIdx.x, c = threadIdx.x;
    __shared__ float red[256];
    float o[2];
#pragma unroll
    for (int h = 0; h < 2; h++) {
        float v = g_num1[h][(size_t)i * D1 + c] / g_den1[h][i];
        float e = eluf(v);
        red[c] = e * e;
        __syncthreads();
        for (int s = 128; s; s >>= 1) {
            if (c < s) red[c] += red[c + s];
            __syncthreads();
        }
        float nrm = sqrtf(red[0]);
        __syncthreads();
        o[h] = e / fmaxf(nrm, 1e-12f) + head_b[h * D1 + c];
    }
    g_z[(size_t)i * D1 + c] = eluf(0.5f * (o[0] + o[1]));
}

__global__ void k_conv(const float* __restrict__ conv_w, const float* __restrict__ conv_cb,
                       const float* __restrict__ conv_a) {
    int i = blockIdx.x, j = threadIdx.x;
    __shared__ float zr[D1];
    __shared__ float wk[132];
    __shared__ float red[128];
    zr[j]       = g_z[(size_t)i * D1 + j];
    zr[j + 128] = g_z[(size_t)i * D1 + j + 128];
    wk[j] = conv_w[j];
    if (j == 0) wk[128] = conv_w[128];
    __syncthreads();
    float acc = conv_cb[0];
#pragma unroll 4
    for (int k = 0; k < 129; k++) acc += zr[j + k] * wk[k];
    g_hc[(size_t)i * D2 + j] = acc;
    __nv_bfloat16 hb = __float2bfloat16(acc);
    g_hchi[(size_t)i * D2 + j] = hb;
    g_hclo[(size_t)i * D2 + j] = __float2bfloat16(acc - __bfloat162float(hb));
    red[j] = acc * conv_a[j];
    __syncthreads();
    for (int s = 64; s; s >>= 1) {
        if (j < s) red[j] += red[j + s];
        __syncthreads();
    }
    if (j == 0) g_s2[i] = red[0];
    __syncthreads();
    red[j] = acc * conv_a[128 + j];
    __syncthreads();
    for (int s = 64; s; s >>= 1) {
        if (j < s) red[j] += red[j + s];
        __syncthreads();
    }
    if (j == 0) g_t2[i] = red[0];
}

__global__ void k_fac2() {
    __shared__ float red[1024];
    float m = -1e30f;
    for (int i = threadIdx.x; i < N_NODES; i += 1024) m = fmaxf(m, g_t2[i]);
    red[threadIdx.x] = m;
    __syncthreads();
    for (int s = 512; s; s >>= 1) {
        if (threadIdx.x < s) red[threadIdx.x] = fmaxf(red[threadIdx.x], red[threadIdx.x + s]);
        __syncthreads();
    }
    float tmax = red[0];
    for (int i = threadIdx.x; i < N_NODES; i += 1024) {
        float s_ = g_s2[i], t_ = g_t2[i];
        float v = s_ + tmax;
        float mm = v > 0.f ? v : (expf(v) - 1.f);
        g_P2[i]  = expf(v - mm);
        g_R2[i]  = expf(-1.f - mm);
        g_Es[i]  = expf(fminf(fmaxf(s_, -60.f), 60.f));
        g_B2[i]  = expf(t_ - tmax);
        g_Et[i]  = expf(fminf(fmaxf(t_, -60.f), 60.f));
        g_th2[i] = -s_;
    }
}

__global__ void k_epi2(const float* __restrict__ conv_b) {
    int i = blockIdx.x, c = threadIdx.x;
    __shared__ float red[128];
    float v = g_num2[(size_t)i * D2 + c] / g_den2[i];
    float e = eluf(v);
    red[c] = e * e;
    __syncthreads();
    for (int s = 64; s; s >>= 1) {
        if (c < s) red[c] += red[c + s];
        __syncthreads();
    }
    float nrm = sqrtf(red[0]);
    g_embed[(size_t)i * D2 + c] = e / fmaxf(nrm, 1e-12f) + conv_b[c];
}

__global__ void k_pred(const int* __restrict__ ts, float* __restrict__ out) {
    int p = blockIdx.x * 8 + (threadIdx.x >> 5);
    if (p >= NPAIRS) return;
    int lane = threadIdx.x & 31;
    int i = ts[2 * p], j = ts[2 * p + 1];
    float a = g_tf[i * 64 + lane] * g_tg[j * 64 + lane]
            + g_tf[i * 64 + 32 + lane] * g_tg[j * 64 + 32 + lane];
#pragma unroll
    for (int o = 16; o; o >>= 1) a += __shfl_xor_sync(0xffffffffu, a, o);
    if (!lane) out[p] = a;
}

extern "C" void kernel_launch(void* const* d_in, const int* in_sizes, int n_in,
                              void* d_out, int out_size) {
    const float* x       = (const float*)d_in[0];
    const int*   adj     = (const int*)d_in[1];
    const int*   tsamp   = (const int*)d_in[2];
    const float* head_W  = (const float*)d_in[3];
    const float* head_a  = (const float*)d_in[4];
    const float* head_b  = (const float*)d_in[5];
    const float* conv_w  = (const float*)d_in[6];
    const float* conv_cb = (const float*)d_in[7];
    const float* conv_a  = (const float*)d_in[8];
    const float* conv_b  = (const float*)d_in[9];
    const float* tf_w1   = (const float*)d_in[10];
    const float* tf_b1   = (const float*)d_in[11];
    const float* tf_w2   = (const float*)d_in[12];
    const float* tf_b2   = (const float*)d_in[13];
    const float* tg_w1   = (const float*)d_in[14];
    const float* tg_b1   = (const float*)d_in[15];
    const float* tg_w2   = (const float*)d_in[16];
    const float* tg_b2   = (const float*)d_in[17];
    float* out = (float*)d_out;

    float *pEmbed, *pMid0, *pMid1, *pTf, *pTg;
    __nv_bfloat16 *pXhi, *pXlo, *pWhi, *pWlo;
    cudaGetSymbolAddress((void**)&pEmbed, g_embed);
    cudaGetSymbolAddress((void**)&pMid0, g_mid);
    pMid1 = pMid0 + (size_t)N_NODES * D2;
    cudaGetSymbolAddress((void**)&pTf, g_tf);
    cudaGetSymbolAddress((void**)&pTg, g_tg);
    cudaGetSymbolAddress((void**)&pXhi, g_xhi);
    cudaGetSymbolAddress((void**)&pXlo, g_xlo);
    cudaGetSymbolAddress((void**)&pWhi, g_Whi);
    cudaGetSymbolAddress((void**)&pWlo, g_Wlo);

    const int SMEM_BIG = 73728 + 2 * 128 * (D1 + 8) * 2;   // 208896
    const int SMEM_SML = 73728 + 2 * 128 * (D2 + 8) * 2;   // 143360
    cudaFuncSetAttribute(k_mma<0>, cudaFuncAttributeMaxDynamicSharedMemorySize, SMEM_BIG);
    cudaFuncSetAttribute(k_mma<1>, cudaFuncAttributeMaxDynamicSharedMemorySize, SMEM_BIG);
    cudaFuncSetAttribute(k_mma<2>, cudaFuncAttributeMaxDynamicSharedMemorySize, SMEM_SML);

    k_pack<<<(N_NODES * NW) / 8, 256>>>(adj);
    k_split<<<(N_NODES * INDIM / 8 + 255) / 256, 256>>>(x, pXhi, pXlo, N_NODES * INDIM);
    k_split<<<(NHEAD * INDIM * D1 / 8 + 255) / 256, 256>>>(head_W, pWhi, pWlo, NHEAD * INDIM * D1);

    k_mma<0><<<dim3(N_NODES / 128, 1, NHEAD), 512, SMEM_BIG>>>(x);
    k_st<<<dim3(N_NODES / 8, NHEAD), 256>>>(head_a);
    k_fac1<<<NHEAD, 1024>>>();
    k_mma<1><<<dim3(N_NODES / 128, 1, NHEAD), 512, SMEM_BIG>>>(x);
    k_epi1<<<N_NODES, 256>>>(head_b);
    k_conv<<<N_NODES, 128>>>(conv_w, conv_cb, conv_a);
    k_fac2<<<1, 1024>>>();
    k_mma<2><<<dim3(N_NODES / 64, 1, 1), 512, SMEM_SML>>>(x);
    k_epi2<<<N_NODES, 128>>>(conv_b);

    k_gemm<1><<<dim3(N_NODES / 64, D2 / 64), 256>>>(pEmbed, tf_w1, tf_b1, pMid0, N_NODES, D2, D2);
    k_gemm<1><<<dim3(N_NODES / 64, 1), 256>>>(pMid0, tf_w2, tf_b2, pTf, N_NODES, D2, 64);
    k_gemm<1><<<dim3(N_NODES / 64, D2 / 64), 256>>>(pEmbed, tg_w1, tg_b1, pMid1, N_NODES, D2, D2);
    k_gemm<1><<<dim3(N_NODES / 64, 1), 256>>>(pMid1, tg_w2, tg_b2, pTg, N_NODES, D2, 64);

    k_pred<<<(NPAIRS + 7) / 8, 256>>>(tsamp, out);
}